// round 1
// baseline (speedup 1.0000x reference)
#include <cuda_runtime.h>
#include <math.h>

// Problem constants
#define B_   64
#define S_   512
#define H_   512
#define E_   1024
#define UV_  2176
#define SD_  128
#define M_   (B_*S_)          // 32768 rows

// -------- scratch (device globals; no allocation allowed) --------
__device__ __align__(16) float g_xn [(size_t)M_*H_];     //  64 MB
__device__ __align__(16) float g_act[(size_t)M_*UV_];    // 285 MB  (u|v|base, silu applied)
__device__ __align__(16) float g_q  [(size_t)M_*SD_];    //  17 MB
__device__ __align__(16) float g_k  [(size_t)M_*SD_];    //  17 MB
__device__ __align__(16) float g_sc [(size_t)B_*S_*S_];  //  64 MB  relu^2 scores
__device__ __align__(16) float g_gt [(size_t)M_*E_];     // 134 MB  u * (P@V)
__device__ __align__(16) float g_sin[S_*64];
__device__ __align__(16) float g_cos[S_*64];

// ---------------- RMS-like norm ----------------
__global__ __launch_bounds__(128) void k_norm(const float* __restrict__ x,
                                              const float* __restrict__ ln_g) {
    int row = blockIdx.x;
    const float4* xr = (const float4*)(x + (size_t)row * H_);
    float4 a = xr[threadIdx.x];
    float ss = a.x*a.x + a.y*a.y + a.z*a.z + a.w*a.w;
    #pragma unroll
    for (int o = 16; o; o >>= 1) ss += __shfl_xor_sync(0xffffffffu, ss, o);
    __shared__ float ws[4];
    if ((threadIdx.x & 31) == 0) ws[threadIdx.x >> 5] = ss;
    __syncthreads();
    float total = ws[0] + ws[1] + ws[2] + ws[3];
    float norm = sqrtf(total * (1.0f / (float)H_));
    float sc = ln_g[0] / fmaxf(norm, 1e-5f);
    float4 o4 = make_float4(a.x*sc, a.y*sc, a.z*sc, a.w*sc);
    ((float4*)(g_xn + (size_t)row * H_))[threadIdx.x] = o4;
}

// ---------------- sin/cos table (match reference fp32 pipeline) ----------------
__global__ void k_sincos() {
    int s = blockIdx.x, d = threadIdx.x;             // d in [0,64)
    float invf = powf(10000.0f, (float)d / 64.0f);   // fp32 pow like reference
    float arg = (float)s * invf;                     // fp32 multiply, same order
    g_sin[s*64 + d] = sinf(arg);
    g_cos[s*64 + d] = cosf(arg);
}

// ---------------- GEMM1: act = silu(xn @ uv_w^T + uv_b) ----------------
// A = g_xn [M,512] rowmajor(K contig), B = uv_w [2176,512] rowmajor(K contig)  -> NT
__global__ __launch_bounds__(256) void k_uv(const float* __restrict__ W,
                                            const float* __restrict__ bias) {
    __shared__ __align__(16) float As[8][128];
    __shared__ __align__(16) float Bs[8][128];
    const int bm = blockIdx.y * 128, bn = blockIdx.x * 128;
    const int t = threadIdx.x, tx = t & 15, ty = t >> 4;
    const int lr = t >> 1, lk = (t & 1) * 4;
    const float* Ap = g_xn + (size_t)(bm + lr) * H_ + lk;
    const float* Bp = W    + (size_t)(bn + lr) * H_ + lk;
    float acc[8][8];
    #pragma unroll
    for (int i = 0; i < 8; i++)
        #pragma unroll
        for (int j = 0; j < 8; j++) acc[i][j] = 0.f;

    for (int k0 = 0; k0 < H_; k0 += 8) {
        float4 av = *(const float4*)(Ap + k0);
        float4 bv = *(const float4*)(Bp + k0);
        __syncthreads();
        As[lk+0][lr]=av.x; As[lk+1][lr]=av.y; As[lk+2][lr]=av.z; As[lk+3][lr]=av.w;
        Bs[lk+0][lr]=bv.x; Bs[lk+1][lr]=bv.y; Bs[lk+2][lr]=bv.z; Bs[lk+3][lr]=bv.w;
        __syncthreads();
        #pragma unroll
        for (int kk = 0; kk < 8; kk++) {
            float a[8], b[8];
            *(float4*)&a[0] = *(const float4*)&As[kk][ty*8];
            *(float4*)&a[4] = *(const float4*)&As[kk][ty*8+4];
            *(float4*)&b[0] = *(const float4*)&Bs[kk][tx*8];
            *(float4*)&b[4] = *(const float4*)&Bs[kk][tx*8+4];
            #pragma unroll
            for (int i = 0; i < 8; i++)
                #pragma unroll
                for (int j = 0; j < 8; j++) acc[i][j] += a[i]*b[j];
        }
    }
    #pragma unroll
    for (int i = 0; i < 8; i++) {
        float* orow = g_act + (size_t)(bm + ty*8 + i) * UV_ + bn + tx*8;
        float r[8];
        #pragma unroll
        for (int j = 0; j < 8; j++) {
            float v = acc[i][j] + bias[bn + tx*8 + j];
            r[j] = v / (1.0f + expf(-v));          // silu
        }
        *(float4*)(orow)     = *(float4*)&r[0];
        *(float4*)(orow + 4) = *(float4*)&r[4];
    }
}

// ---------------- gamma/beta + RoPE -> q,k ----------------
__global__ __launch_bounds__(64) void k_rope(const float* __restrict__ gamma,
                                             const float* __restrict__ beta) {
    int row = blockIdx.x;          // b*S + s
    int s = row & (S_ - 1);
    int d = threadIdx.x;           // [0,64)
    const float* base = g_act + (size_t)row * UV_ + 2*E_;
    float b1 = base[d], b2 = base[d + 64];
    float sn = g_sin[s*64 + d], cs = g_cos[s*64 + d];
    // q channel (gamma[0], beta[0])
    float x1 = b1 * gamma[d]       + beta[d];
    float x2 = b2 * gamma[d + 64]  + beta[d + 64];
    g_q[(size_t)row*SD_ + d]      = x1*cs - x2*sn;
    g_q[(size_t)row*SD_ + d + 64] = x2*cs + x1*sn;
    // k channel (gamma[1], beta[1])
    float y1 = b1 * gamma[128 + d]      + beta[128 + d];
    float y2 = b2 * gamma[128 + 64 + d] + beta[128 + 64 + d];
    g_k[(size_t)row*SD_ + d]      = y1*cs - y2*sn;
    g_k[(size_t)row*SD_ + d + 64] = y2*cs + y1*sn;
}

// ---------------- scores = relu((q@k^T + bias)/sqrt(128))^2 ----------------
__global__ __launch_bounds__(256) void k_qk(const float* __restrict__ wb) {
    __shared__ __align__(16) float As[8][128];
    __shared__ __align__(16) float Bs[8][128];
    const int b = blockIdx.z;
    const int bm = blockIdx.y * 128, bn = blockIdx.x * 128;
    const int t = threadIdx.x, tx = t & 15, ty = t >> 4;
    const int lr = t >> 1, lk = (t & 1) * 4;
    const float* Ap = g_q + (size_t)b*S_*SD_ + (size_t)(bm + lr)*SD_ + lk;
    const float* Bp = g_k + (size_t)b*S_*SD_ + (size_t)(bn + lr)*SD_ + lk;
    float acc[8][8];
    #pragma unroll
    for (int i = 0; i < 8; i++)
        #pragma unroll
        for (int j = 0; j < 8; j++) acc[i][j] = 0.f;

    for (int k0 = 0; k0 < SD_; k0 += 8) {
        float4 av = *(const float4*)(Ap + k0);
        float4 bv = *(const float4*)(Bp + k0);
        __syncthreads();
        As[lk+0][lr]=av.x; As[lk+1][lr]=av.y; As[lk+2][lr]=av.z; As[lk+3][lr]=av.w;
        Bs[lk+0][lr]=bv.x; Bs[lk+1][lr]=bv.y; Bs[lk+2][lr]=bv.z; Bs[lk+3][lr]=bv.w;
        __syncthreads();
        #pragma unroll
        for (int kk = 0; kk < 8; kk++) {
            float a[8], bb[8];
            *(float4*)&a[0]  = *(const float4*)&As[kk][ty*8];
            *(float4*)&a[4]  = *(const float4*)&As[kk][ty*8+4];
            *(float4*)&bb[0] = *(const float4*)&Bs[kk][tx*8];
            *(float4*)&bb[4] = *(const float4*)&Bs[kk][tx*8+4];
            #pragma unroll
            for (int i = 0; i < 8; i++)
                #pragma unroll
                for (int j = 0; j < 8; j++) acc[i][j] += a[i]*bb[j];
        }
    }
    #pragma unroll
    for (int i = 0; i < 8; i++) {
        int m = bm + ty*8 + i;
        float* orow = g_sc + (size_t)b*S_*S_ + (size_t)m*S_ + bn + tx*8;
        float r[8];
        #pragma unroll
        for (int j = 0; j < 8; j++) {
            int n = bn + tx*8 + j;
            float v = (acc[i][j] + wb[n - m + (S_ - 1)]) / 11.313708498984761f;
            float rl = fmaxf(v, 0.0f);
            r[j] = rl * rl;
        }
        *(float4*)(orow)     = *(float4*)&r[0];
        *(float4*)(orow + 4) = *(float4*)&r[4];
    }
}

// ---------------- gated = u * (scores @ v) ----------------
// A = scores[b] [512,512] K contig (NT-style A load); B = v slice of g_act, N contig (NN B load)
__global__ __launch_bounds__(256) void k_pv() {
    __shared__ __align__(16) float As[8][128];
    __shared__ __align__(16) float Bs[8][128];
    const int b = blockIdx.z;
    const int bm = blockIdx.y * 128, bn = blockIdx.x * 128;   // bn over E_=1024
    const int t = threadIdx.x, tx = t & 15, ty = t >> 4;
    const int ar = t >> 1, ak = (t & 1) * 4;
    const int krow = t >> 5, bcol = (t & 31) * 4;
    const float* Ap = g_sc  + (size_t)b*S_*S_ + (size_t)(bm + ar)*S_ + ak;
    const float* Bb = g_act + (size_t)b*S_*UV_ + E_;          // v slice base for this batch
    float acc[8][8];
    #pragma unroll
    for (int i = 0; i < 8; i++)
        #pragma unroll
        for (int j = 0; j < 8; j++) acc[i][j] = 0.f;

    for (int k0 = 0; k0 < S_; k0 += 8) {
        float4 av = *(const float4*)(Ap + k0);
        float4 bv = *(const float4*)(Bb + (size_t)(k0 + krow)*UV_ + bn + bcol);
        __syncthreads();
        As[ak+0][ar]=av.x; As[ak+1][ar]=av.y; As[ak+2][ar]=av.z; As[ak+3][ar]=av.w;
        *(float4*)&Bs[krow][bcol] = bv;
        __syncthreads();
        #pragma unroll
        for (int kk = 0; kk < 8; kk++) {
            float a[8], bb[8];
            *(float4*)&a[0]  = *(const float4*)&As[kk][ty*8];
            *(float4*)&a[4]  = *(const float4*)&As[kk][ty*8+4];
            *(float4*)&bb[0] = *(const float4*)&Bs[kk][tx*8];
            *(float4*)&bb[4] = *(const float4*)&Bs[kk][tx*8+4];
            #pragma unroll
            for (int i = 0; i < 8; i++)
                #pragma unroll
                for (int j = 0; j < 8; j++) acc[i][j] += a[i]*bb[j];
        }
    }
    #pragma unroll
    for (int i = 0; i < 8; i++) {
        size_t row = (size_t)b*S_ + bm + ty*8 + i;
        const float* urow = g_act + row*UV_ + bn + tx*8;     // u slice
        float* orow = g_gt + row*E_ + bn + tx*8;
        float4 u0 = *(const float4*)(urow);
        float4 u1 = *(const float4*)(urow + 4);
        float4 r0 = make_float4(u0.x*acc[i][0], u0.y*acc[i][1], u0.z*acc[i][2], u0.w*acc[i][3]);
        float4 r1 = make_float4(u1.x*acc[i][4], u1.y*acc[i][5], u1.z*acc[i][6], u1.w*acc[i][7]);
        *(float4*)(orow)     = r0;
        *(float4*)(orow + 4) = r1;
    }
}

// ---------------- out = gated @ o_w^T + o_b + x ----------------
__global__ __launch_bounds__(256) void k_out(const float* __restrict__ W,
                                             const float* __restrict__ ob,
                                             const float* __restrict__ x,
                                             float* __restrict__ out) {
    __shared__ __align__(16) float As[8][128];
    __shared__ __align__(16) float Bs[8][128];
    const int bm = blockIdx.y * 128, bn = blockIdx.x * 128;
    const int t = threadIdx.x, tx = t & 15, ty = t >> 4;
    const int lr = t >> 1, lk = (t & 1) * 4;
    const float* Ap = g_gt + (size_t)(bm + lr)*E_ + lk;
    const float* Bp = W    + (size_t)(bn + lr)*E_ + lk;
    float acc[8][8];
    #pragma unroll
    for (int i = 0; i < 8; i++)
        #pragma unroll
        for (int j = 0; j < 8; j++) acc[i][j] = 0.f;

    for (int k0 = 0; k0 < E_; k0 += 8) {
        float4 av = *(const float4*)(Ap + k0);
        float4 bv = *(const float4*)(Bp + k0);
        __syncthreads();
        As[lk+0][lr]=av.x; As[lk+1][lr]=av.y; As[lk+2][lr]=av.z; As[lk+3][lr]=av.w;
        Bs[lk+0][lr]=bv.x; Bs[lk+1][lr]=bv.y; Bs[lk+2][lr]=bv.z; Bs[lk+3][lr]=bv.w;
        __syncthreads();
        #pragma unroll
        for (int kk = 0; kk < 8; kk++) {
            float a[8], bb[8];
            *(float4*)&a[0]  = *(const float4*)&As[kk][ty*8];
            *(float4*)&a[4]  = *(const float4*)&As[kk][ty*8+4];
            *(float4*)&bb[0] = *(const float4*)&Bs[kk][tx*8];
            *(float4*)&bb[4] = *(const float4*)&Bs[kk][tx*8+4];
            #pragma unroll
            for (int i = 0; i < 8; i++)
                #pragma unroll
                for (int j = 0; j < 8; j++) acc[i][j] += a[i]*bb[j];
        }
    }
    #pragma unroll
    for (int i = 0; i < 8; i++) {
        size_t m = (size_t)bm + ty*8 + i;
        const float* xrow = x + m*H_ + bn + tx*8;
        float* orow = out + m*H_ + bn + tx*8;
        float4 x0 = *(const float4*)(xrow);
        float4 x1 = *(const float4*)(xrow + 4);
        float r[8];
        #pragma unroll
        for (int j = 0; j < 8; j++) r[j] = acc[i][j] + ob[bn + tx*8 + j];
        float4 r0 = make_float4(r[0]+x0.x, r[1]+x0.y, r[2]+x0.z, r[3]+x0.w);
        float4 r1 = make_float4(r[4]+x1.x, r[5]+x1.y, r[6]+x1.z, r[7]+x1.w);
        *(float4*)(orow)     = r0;
        *(float4*)(orow + 4) = r1;
    }
}

extern "C" void kernel_launch(void* const* d_in, const int* in_sizes, int n_in,
                              void* d_out, int out_size) {
    const float* x    = (const float*)d_in[0];
    const float* ln_g = (const float*)d_in[1];
    const float* uv_w = (const float*)d_in[2];
    const float* uv_b = (const float*)d_in[3];
    const float* gam  = (const float*)d_in[4];
    const float* bet  = (const float*)d_in[5];
    const float* wb   = (const float*)d_in[6];
    const float* o_w  = (const float*)d_in[7];
    const float* o_b  = (const float*)d_in[8];
    float* out = (float*)d_out;

    k_norm  <<<M_, 128>>>(x, ln_g);
    k_sincos<<<S_, 64>>>();
    k_uv    <<<dim3(UV_/128, M_/128), 256>>>(uv_w, uv_b);
    k_rope  <<<M_, 64>>>(gam, bet);
    k_qk    <<<dim3(S_/128, S_/128, B_), 256>>>(wb);
    k_pv    <<<dim3(E_/128, S_/128, B_), 256>>>();
    k_out   <<<dim3(H_/128, M_/128), 256>>>(o_w, o_b, x, out);
}

// round 3
// speedup vs baseline: 1.7936x; 1.7936x over previous
#include <cuda_runtime.h>
#include <cuda_bf16.h>
#include <math.h>
#include <stdint.h>

#define B_   64
#define S_   512
#define H_   512
#define E_   1024
#define UV_  2176
#define SD_  128
#define M_   (B_*S_)

typedef __nv_bfloat16 bf16;

// ---------------- scratch (device globals) ----------------
__device__ __align__(16) bf16  g_xnh[(size_t)M_*H_];
__device__ __align__(16) bf16  g_xnl[(size_t)M_*H_];
__device__ __align__(16) bf16  g_wh [(size_t)UV_*H_];
__device__ __align__(16) bf16  g_wl [(size_t)UV_*H_];
__device__ __align__(16) bf16  g_owh[(size_t)H_*E_];
__device__ __align__(16) bf16  g_owl[(size_t)H_*E_];
__device__ __align__(16) float g_u  [(size_t)M_*E_];
__device__ __align__(16) float g_v  [(size_t)M_*E_];      // [b][t][e] fp32
__device__ __align__(16) bf16  g_vth[(size_t)B_*E_*S_];   // [b][e][t]
__device__ __align__(16) bf16  g_vtl[(size_t)B_*E_*S_];
__device__ __align__(16) float g_base[(size_t)M_*SD_];
__device__ __align__(16) bf16  g_qh[(size_t)M_*SD_];
__device__ __align__(16) bf16  g_ql[(size_t)M_*SD_];
__device__ __align__(16) bf16  g_kh[(size_t)M_*SD_];
__device__ __align__(16) bf16  g_kl[(size_t)M_*SD_];
__device__ __align__(16) bf16  g_ph[(size_t)B_*S_*S_];
__device__ __align__(16) bf16  g_pl[(size_t)B_*S_*S_];
__device__ __align__(16) bf16  g_gth[(size_t)M_*E_];
__device__ __align__(16) bf16  g_gtl[(size_t)M_*E_];
__device__ float g_sin[S_*64];
__device__ float g_cos[S_*64];

// ---------------- helpers ----------------
__device__ __forceinline__ uint32_t smem_u32(const void* p) {
    uint32_t a;
    asm("{ .reg .u64 t; cvta.to.shared.u64 t, %1; cvt.u32.u64 %0, t; }" : "=r"(a) : "l"(p));
    return a;
}
__device__ __forceinline__ void cpa16(uint32_t s, const void* g) {
    asm volatile("cp.async.cg.shared.global [%0], [%1], 16;" :: "r"(s), "l"(g));
}
#define CP_COMMIT() asm volatile("cp.async.commit_group;")
#define CP_WAIT(n)  asm volatile("cp.async.wait_group %0;" :: "n"(n) : "memory")

__device__ __forceinline__ void ldm4(uint32_t* r, uint32_t a) {
    asm volatile("ldmatrix.sync.aligned.m8n8.x4.shared.b16 {%0,%1,%2,%3},[%4];"
                 : "=r"(r[0]), "=r"(r[1]), "=r"(r[2]), "=r"(r[3]) : "r"(a));
}
__device__ __forceinline__ void mma16816(float* d, const uint32_t* a, const uint32_t* b) {
    asm volatile("mma.sync.aligned.m16n8k16.row.col.f32.bf16.bf16.f32 "
                 "{%0,%1,%2,%3},{%4,%5,%6,%7},{%8,%9},{%0,%1,%2,%3};"
                 : "+f"(d[0]), "+f"(d[1]), "+f"(d[2]), "+f"(d[3])
                 : "r"(a[0]), "r"(a[1]), "r"(a[2]), "r"(a[3]), "r"(b[0]), "r"(b[1]));
}
__device__ __forceinline__ void split2(float x, bf16& h, bf16& l) {
    h = __float2bfloat16_rn(x);
    l = __float2bfloat16_rn(x - __bfloat162float(h));
}
__device__ __forceinline__ uint32_t pack_split(float v0, float v1, uint32_t& lo) {
    bf16 h0, l0, h1, l1;
    split2(v0, h0, l0); split2(v1, h1, l1);
    lo = (uint32_t)__bfloat16_as_ushort(l0) | ((uint32_t)__bfloat16_as_ushort(l1) << 16);
    return (uint32_t)__bfloat16_as_ushort(h0) | ((uint32_t)__bfloat16_as_ushort(h1) << 16);
}

// ---------------- norm -> split bf16 ----------------
__global__ __launch_bounds__(128) void k_norm(const float* __restrict__ x,
                                              const float* __restrict__ ln_g) {
    int row = blockIdx.x;
    const float4* xr = (const float4*)(x + (size_t)row * H_);
    float4 a = xr[threadIdx.x];
    float ss = a.x*a.x + a.y*a.y + a.z*a.z + a.w*a.w;
    #pragma unroll
    for (int o = 16; o; o >>= 1) ss += __shfl_xor_sync(0xffffffffu, ss, o);
    __shared__ float ws[4];
    if ((threadIdx.x & 31) == 0) ws[threadIdx.x >> 5] = ss;
    __syncthreads();
    float total = ws[0] + ws[1] + ws[2] + ws[3];
    float norm = sqrtf(total * (1.0f / (float)H_));
    float sc = ln_g[0] / fmaxf(norm, 1e-5f);
    float v[4] = {a.x*sc, a.y*sc, a.z*sc, a.w*sc};
    bf16 h[4], l[4];
    #pragma unroll
    for (int i = 0; i < 4; i++) split2(v[i], h[i], l[i]);
    size_t off = (size_t)row * H_ + threadIdx.x * 4;
    *(uint2*)(g_xnh + off) = *(uint2*)h;
    *(uint2*)(g_xnl + off) = *(uint2*)l;
}

// ---------------- generic fp32 -> bf16 hi/lo split ----------------
__global__ __launch_bounds__(256) void k_split(const float* __restrict__ src,
                                               bf16* __restrict__ dh, bf16* __restrict__ dl,
                                               int n4) {
    int i = blockIdx.x * blockDim.x + threadIdx.x;
    if (i >= n4) return;
    float4 a = ((const float4*)src)[i];
    float v[4] = {a.x, a.y, a.z, a.w};
    bf16 h[4], l[4];
    #pragma unroll
    for (int k = 0; k < 4; k++) split2(v[k], h[k], l[k]);
    *(uint2*)(dh + (size_t)i*4) = *(uint2*)h;
    *(uint2*)(dl + (size_t)i*4) = *(uint2*)l;
}

// ---------------- sin/cos table: double-precision provenance ----------------
__global__ void k_sincos() {
    int s = blockIdx.x, d = threadIdx.x;
    double invf_d = pow(10000.0, (double)d / 64.0);
    float invf = (float)invf_d;            // correctly-rounded fp32 inv_freq
    float arg = (float)s * invf;           // fp32 multiply, same as reference
    double a = (double)arg;
    g_sin[s*64 + d] = (float)sin(a);
    g_cos[s*64 + d] = (float)cos(a);
}

// ---------------- gamma/beta + RoPE -> split q,k ----------------
__global__ __launch_bounds__(64) void k_rope(const float* __restrict__ gamma,
                                             const float* __restrict__ beta) {
    int row = blockIdx.x;
    int s = row & (S_ - 1);
    int d = threadIdx.x;
    const float* base = g_base + (size_t)row * SD_;
    float b1 = base[d], b2 = base[d + 64];
    float sn = g_sin[s*64 + d], cs = g_cos[s*64 + d];
    float x1 = b1 * gamma[d]      + beta[d];
    float x2 = b2 * gamma[d + 64] + beta[d + 64];
    float q0 = x1*cs - x2*sn, q1 = x2*cs + x1*sn;
    float y1 = b1 * gamma[128 + d]      + beta[128 + d];
    float y2 = b2 * gamma[128 + 64 + d] + beta[128 + 64 + d];
    float k0 = y1*cs - y2*sn, k1 = y2*cs + y1*sn;
    size_t o = (size_t)row * SD_;
    bf16 h, l;
    split2(q0, h, l); g_qh[o+d] = h;    g_ql[o+d] = l;
    split2(q1, h, l); g_qh[o+d+64] = h; g_ql[o+d+64] = l;
    split2(k0, h, l); g_kh[o+d] = h;    g_kl[o+d] = l;
    split2(k1, h, l); g_kh[o+d+64] = h; g_kl[o+d+64] = l;
}

// ---------------- v transpose + split: [b][t][e] fp32 -> [b][e][t] bf16 hi/lo ----------------
__global__ __launch_bounds__(256) void k_vt() {
    __shared__ float tile[32][33];
    int e0 = blockIdx.x * 32, t0 = blockIdx.y * 32, b = blockIdx.z;
    int tx = threadIdx.x, ty = threadIdx.y;   // block (32,8)
    #pragma unroll
    for (int i = 0; i < 4; i++) {
        int t = t0 + ty + i*8;
        tile[ty + i*8][tx] = g_v[((size_t)b*S_ + t)*E_ + e0 + tx];
    }
    __syncthreads();
    #pragma unroll
    for (int i = 0; i < 4; i++) {
        int e = e0 + ty + i*8;
        float x = tile[tx][ty + i*8];
        bf16 h, l; split2(x, h, l);
        size_t o = ((size_t)b*E_ + e)*S_ + t0 + tx;
        g_vth[o] = h; g_vtl[o] = l;
    }
}

// =================================================================
// mma.sync bf16 GEMM: 128x128 CTA tile, 8 warps (4m x 2n, 32x64 each),
// BK=32 double-buffered cp.async. D += Ah*Bh + Ah*Bl + Al*Bh.
// All operands stored [row][K] with K contiguous ("row.col" NT form).
// EPI: 0=uv  1=qk  2=pv  3=out
// =================================================================
#define KPAD   40            // bf16 elements per smem row (32 + 8 pad)
#define ARR_B  (128*KPAD*2)  // 10240 bytes per operand array
#define BUF_B  (4*ARR_B)     // 40960 per stage
#define SMEMSZ (2*BUF_B)     // 81920

template<int EPI>
__global__ __launch_bounds__(256) void k_gemm(const float* __restrict__ aux,
                                              const float* __restrict__ aux2,
                                              float* __restrict__ fout) {
    constexpr int LD = (EPI==0) ? 512 : (EPI==1) ? 128 : (EPI==2) ? 512 : 1024;
    constexpr int NS = LD / 32;

    extern __shared__ __align__(16) char smem[];
    const uint32_t sb = smem_u32(smem);
    const int tid = threadIdx.x, wid = tid >> 5, lane = tid & 31;
    const int bm = blockIdx.y * 128, bn = blockIdx.x * 128, bz = blockIdx.z;

    const bf16 *Ah, *Al, *Bh, *Bl;
    if (EPI == 0)      { Ah = g_xnh; Al = g_xnl; Bh = g_wh;  Bl = g_wl; }
    else if (EPI == 1) { size_t o = (size_t)bz*S_*SD_;
                         Ah = g_qh+o; Al = g_ql+o; Bh = g_kh+o; Bl = g_kl+o; }
    else if (EPI == 2) { size_t oa = (size_t)bz*S_*S_, ob = (size_t)bz*E_*S_;
                         Ah = g_ph+oa; Al = g_pl+oa; Bh = g_vth+ob; Bl = g_vtl+ob; }
    else               { Ah = g_gth; Al = g_gtl; Bh = g_owh; Bl = g_owl; }

    // --- load mapping: thread -> row (tid/2), two 16B chunks at col ((tid&1)*16 | +8)
    const int lrow = tid >> 1;
    const int lc   = (tid & 1) * 16;
    const bf16* gAh = Ah + (size_t)(bm + lrow) * LD + lc;
    const bf16* gAl = Al + (size_t)(bm + lrow) * LD + lc;
    const bf16* gBh = Bh + (size_t)(bn + lrow) * LD + lc;
    const bf16* gBl = Bl + (size_t)(bn + lrow) * LD + lc;
    const uint32_t srow = sb + lrow * (KPAD*2) + lc * 2;

    auto load_stage = [&](int s) {
        const uint32_t d = srow + (s & 1) * BUF_B;
        const int off = s * 32;
        cpa16(d + 0*ARR_B,      gAh + off); cpa16(d + 0*ARR_B + 16, gAh + off + 8);
        cpa16(d + 1*ARR_B,      gAl + off); cpa16(d + 1*ARR_B + 16, gAl + off + 8);
        cpa16(d + 2*ARR_B,      gBh + off); cpa16(d + 2*ARR_B + 16, gBh + off + 8);
        cpa16(d + 3*ARR_B,      gBl + off); cpa16(d + 3*ARR_B + 16, gBl + off + 8);
    };

    load_stage(0); CP_COMMIT();
    load_stage(1); CP_COMMIT();

    const int am = (wid & 3) * 32;      // warp rows
    const int an = (wid >> 2) * 64;     // warp cols
    float acc[2][8][4];
    #pragma unroll
    for (int mt = 0; mt < 2; mt++)
        #pragma unroll
        for (int nt = 0; nt < 8; nt++)
            #pragma unroll
            for (int j = 0; j < 4; j++) acc[mt][nt][j] = 0.f;

    // ldmatrix per-thread address pieces
    const int a_row = am + (lane & 15);
    const int a_col = (lane >> 4) * 8;
    const int b_row = an + ((lane >> 4) & 1) * 8 + (lane & 7);
    const int b_col = ((lane >> 3) & 1) * 8;

    for (int s = 0; s < NS; s++) {
        if (s + 1 < NS) { CP_WAIT(1); } else { CP_WAIT(0); }
        __syncthreads();
        const uint32_t bufb = sb + (s & 1) * BUF_B;
        #pragma unroll
        for (int kk = 0; kk < 32; kk += 16) {
            uint32_t ah[2][4], al[2][4];
            #pragma unroll
            for (int mt = 0; mt < 2; mt++) {
                uint32_t ad = bufb + (a_row + mt*16) * (KPAD*2) + (kk + a_col) * 2;
                ldm4(ah[mt], ad);
                ldm4(al[mt], ad + ARR_B);
            }
            uint32_t bh[8][2], bl[8][2];
            #pragma unroll
            for (int n2 = 0; n2 < 4; n2++) {
                uint32_t bd = bufb + 2*ARR_B + (b_row + n2*16) * (KPAD*2) + (kk + b_col) * 2;
                uint32_t r[4];
                ldm4(r, bd);
                bh[n2*2][0]=r[0]; bh[n2*2][1]=r[1]; bh[n2*2+1][0]=r[2]; bh[n2*2+1][1]=r[3];
                ldm4(r, bd + ARR_B);
                bl[n2*2][0]=r[0]; bl[n2*2][1]=r[1]; bl[n2*2+1][0]=r[2]; bl[n2*2+1][1]=r[3];
            }
            #pragma unroll
            for (int mt = 0; mt < 2; mt++)
                #pragma unroll
                for (int nt = 0; nt < 8; nt++) {
                    mma16816(acc[mt][nt], ah[mt], bh[nt]);
                    mma16816(acc[mt][nt], ah[mt], bl[nt]);
                    mma16816(acc[mt][nt], al[mt], bh[nt]);
                }
        }
        __syncthreads();
        if (s + 2 < NS) { load_stage(s + 2); CP_COMMIT(); }
    }

    // -------- epilogue --------
    const int r4 = lane >> 2, c2 = (lane & 3) * 2;
    #pragma unroll
    for (int mt = 0; mt < 2; mt++)
        #pragma unroll
        for (int half = 0; half < 2; half++) {
            const int row = bm + am + mt*16 + half*8 + r4;   // row within A-dim
            #pragma unroll
            for (int nt = 0; nt < 8; nt++) {
                const int col = bn + an + nt*8 + c2;
                float v0 = acc[mt][nt][half*2 + 0];
                float v1 = acc[mt][nt][half*2 + 1];

                if (EPI == 0) {
                    float a0 = v0 + aux[col], a1 = v1 + aux[col+1];
                    a0 = a0 / (1.0f + expf(-a0));
                    a1 = a1 / (1.0f + expf(-a1));
                    if (col < E_)
                        *(float2*)(g_u + (size_t)row*E_ + col) = make_float2(a0, a1);
                    else if (col < 2*E_)
                        *(float2*)(g_v + (size_t)row*E_ + (col - E_)) = make_float2(a0, a1);
                    else
                        *(float2*)(g_base + (size_t)row*SD_ + (col - 2*E_)) = make_float2(a0, a1);
                } else if (EPI == 1) {
                    float a0 = (v0 + aux[col     - row + (S_-1)]) / 11.313708498984761f;
                    float a1 = (v1 + aux[col + 1 - row + (S_-1)]) / 11.313708498984761f;
                    a0 = fmaxf(a0, 0.f); a1 = fmaxf(a1, 0.f);
                    a0 *= a0; a1 *= a1;
                    uint32_t lo, hi = pack_split(a0, a1, lo);
                    size_t o = (size_t)bz*S_*S_ + (size_t)row*S_ + col;
                    *(uint32_t*)(g_ph + o) = hi;
                    *(uint32_t*)(g_pl + o) = lo;
                } else if (EPI == 2) {
                    size_t rr = (size_t)bz*S_ + row;
                    float u0 = g_u[rr*E_ + col], u1 = g_u[rr*E_ + col + 1];
                    float a0 = v0 * u0, a1 = v1 * u1;
                    uint32_t lo, hi = pack_split(a0, a1, lo);
                    size_t o = rr*E_ + col;
                    *(uint32_t*)(g_gth + o) = hi;
                    *(uint32_t*)(g_gtl + o) = lo;
                } else {
                    size_t o = (size_t)row*H_ + col;
                    float a0 = v0 + aux[col]     + aux2[o];
                    float a1 = v1 + aux[col + 1] + aux2[o + 1];
                    *(float2*)(fout + o) = make_float2(a0, a1);
                }
            }
        }
}

// ---------------- launch ----------------
extern "C" void kernel_launch(void* const* d_in, const int* in_sizes, int n_in,
                              void* d_out, int out_size) {
    const float* x    = (const float*)d_in[0];
    const float* ln_g = (const float*)d_in[1];
    const float* uv_w = (const float*)d_in[2];
    const float* uv_b = (const float*)d_in[3];
    const float* gam  = (const float*)d_in[4];
    const float* bet  = (const float*)d_in[5];
    const float* wb   = (const float*)d_in[6];
    const float* o_w  = (const float*)d_in[7];
    const float* o_b  = (const float*)d_in[8];
    float* out = (float*)d_out;

    static bool attr_done = false;
    if (!attr_done) {
        cudaFuncSetAttribute(k_gemm<0>, cudaFuncAttributeMaxDynamicSharedMemorySize, SMEMSZ);
        cudaFuncSetAttribute(k_gemm<1>, cudaFuncAttributeMaxDynamicSharedMemorySize, SMEMSZ);
        cudaFuncSetAttribute(k_gemm<2>, cudaFuncAttributeMaxDynamicSharedMemorySize, SMEMSZ);
        cudaFuncSetAttribute(k_gemm<3>, cudaFuncAttributeMaxDynamicSharedMemorySize, SMEMSZ);
        attr_done = true;
    }

    bf16 *wh, *wl, *owh, *owl;
    cudaGetSymbolAddress((void**)&wh,  g_wh);
    cudaGetSymbolAddress((void**)&wl,  g_wl);
    cudaGetSymbolAddress((void**)&owh, g_owh);
    cudaGetSymbolAddress((void**)&owl, g_owl);

    k_norm  <<<M_, 128>>>(x, ln_g);
    k_split <<<(UV_*H_/4 + 255)/256, 256>>>(uv_w, wh, wl, UV_*H_/4);
    k_split <<<(H_*E_/4 + 255)/256, 256>>>(o_w, owh, owl, H_*E_/4);
    k_sincos<<<S_, 64>>>();

    k_gemm<0><<<dim3(UV_/128, M_/128), 256, SMEMSZ>>>(uv_b, nullptr, nullptr);
    k_rope  <<<M_, 64>>>(gam, bet);
    k_vt    <<<dim3(E_/32, S_/32, B_), dim3(32, 8)>>>();
    k_gemm<1><<<dim3(S_/128, S_/128, B_), 256, SMEMSZ>>>(wb, nullptr, nullptr);
    k_gemm<2><<<dim3(E_/128, S_/128, B_), 256, SMEMSZ>>>(nullptr, nullptr, nullptr);
    k_gemm<3><<<dim3(H_/128, M_/128), 256, SMEMSZ>>>(o_b, x, out);
}

// round 4
// speedup vs baseline: 2.2218x; 1.2387x over previous
#include <cuda_runtime.h>
#include <cuda_fp16.h>
#include <math.h>
#include <stdint.h>

#define B_   64
#define S_   512
#define H_   512
#define E_   1024
#define UV_  2176
#define SD_  128
#define M_   (B_*S_)

typedef __half fp16;

// ---------------- scratch (device globals) ----------------
__device__ __align__(16) fp16  g_xnh[(size_t)M_*H_];
__device__ __align__(16) fp16  g_xnl[(size_t)M_*H_];
__device__ __align__(16) fp16  g_wh [(size_t)UV_*H_];
__device__ __align__(16) fp16  g_wl [(size_t)UV_*H_];
__device__ __align__(16) fp16  g_owh[(size_t)H_*E_];
__device__ __align__(16) fp16  g_owl[(size_t)H_*E_];
__device__ __align__(16) float g_u  [(size_t)M_*E_];
__device__ __align__(16) float g_v  [(size_t)M_*E_];      // [b][t][e] fp32
__device__ __align__(16) fp16  g_vth[(size_t)B_*E_*S_];   // [b][e][t]
__device__ __align__(16) fp16  g_vtl[(size_t)B_*E_*S_];
__device__ __align__(16) float g_base[(size_t)M_*SD_];
__device__ __align__(16) fp16  g_qh[(size_t)M_*SD_];
__device__ __align__(16) fp16  g_ql[(size_t)M_*SD_];
__device__ __align__(16) fp16  g_kh[(size_t)M_*SD_];
__device__ __align__(16) fp16  g_kl[(size_t)M_*SD_];
__device__ __align__(16) fp16  g_p [(size_t)B_*S_*S_];    // scores, single fp16
__device__ __align__(16) fp16  g_gt[(size_t)M_*E_];       // gated, single fp16
__device__ float g_sin[S_*64];
__device__ float g_cos[S_*64];

// ---------------- helpers ----------------
__device__ __forceinline__ uint32_t smem_u32(const void* p) {
    uint32_t a;
    asm("{ .reg .u64 t; cvta.to.shared.u64 t, %1; cvt.u32.u64 %0, t; }" : "=r"(a) : "l"(p));
    return a;
}
__device__ __forceinline__ void cpa16(uint32_t s, const void* g) {
    asm volatile("cp.async.cg.shared.global [%0], [%1], 16;" :: "r"(s), "l"(g));
}
#define CP_COMMIT() asm volatile("cp.async.commit_group;")
#define CP_WAIT(n)  asm volatile("cp.async.wait_group %0;" :: "n"(n) : "memory")

__device__ __forceinline__ void ldm4(uint32_t* r, uint32_t a) {
    asm volatile("ldmatrix.sync.aligned.m8n8.x4.shared.b16 {%0,%1,%2,%3},[%4];"
                 : "=r"(r[0]), "=r"(r[1]), "=r"(r[2]), "=r"(r[3]) : "r"(a));
}
__device__ __forceinline__ void mma16816(float* d, const uint32_t* a, const uint32_t* b) {
    asm volatile("mma.sync.aligned.m16n8k16.row.col.f32.f16.f16.f32 "
                 "{%0,%1,%2,%3},{%4,%5,%6,%7},{%8,%9},{%0,%1,%2,%3};"
                 : "+f"(d[0]), "+f"(d[1]), "+f"(d[2]), "+f"(d[3])
                 : "r"(a[0]), "r"(a[1]), "r"(a[2]), "r"(a[3]), "r"(b[0]), "r"(b[1]));
}
__device__ __forceinline__ void split2(float x, fp16& h, fp16& l) {
    h = __float2half_rn(x);
    l = __float2half_rn(x - __half2float(h));
}
__device__ __forceinline__ uint32_t packh(fp16 a, fp16 b) {
    return (uint32_t)__half_as_ushort(a) | ((uint32_t)__half_as_ushort(b) << 16);
}

// ---------------- norm -> split fp16 ----------------
__global__ __launch_bounds__(128) void k_norm(const float* __restrict__ x,
                                              const float* __restrict__ ln_g) {
    int row = blockIdx.x;
    const float4* xr = (const float4*)(x + (size_t)row * H_);
    float4 a = xr[threadIdx.x];
    float ss = a.x*a.x + a.y*a.y + a.z*a.z + a.w*a.w;
    #pragma unroll
    for (int o = 16; o; o >>= 1) ss += __shfl_xor_sync(0xffffffffu, ss, o);
    __shared__ float ws[4];
    if ((threadIdx.x & 31) == 0) ws[threadIdx.x >> 5] = ss;
    __syncthreads();
    float total = ws[0] + ws[1] + ws[2] + ws[3];
    float norm = sqrtf(total * (1.0f / (float)H_));
    float sc = ln_g[0] / fmaxf(norm, 1e-5f);
    float v[4] = {a.x*sc, a.y*sc, a.z*sc, a.w*sc};
    fp16 h[4], l[4];
    #pragma unroll
    for (int i = 0; i < 4; i++) split2(v[i], h[i], l[i]);
    size_t off = (size_t)row * H_ + threadIdx.x * 4;
    *(uint2*)(g_xnh + off) = *(uint2*)h;
    *(uint2*)(g_xnl + off) = *(uint2*)l;
}

// ---------------- generic fp32 -> fp16 hi/lo split ----------------
__global__ __launch_bounds__(256) void k_split(const float* __restrict__ src,
                                               fp16* __restrict__ dh, fp16* __restrict__ dl,
                                               int n4) {
    int i = blockIdx.x * blockDim.x + threadIdx.x;
    if (i >= n4) return;
    float4 a = ((const float4*)src)[i];
    float v[4] = {a.x, a.y, a.z, a.w};
    fp16 h[4], l[4];
    #pragma unroll
    for (int k = 0; k < 4; k++) split2(v[k], h[k], l[k]);
    *(uint2*)(dh + (size_t)i*4) = *(uint2*)h;
    *(uint2*)(dl + (size_t)i*4) = *(uint2*)l;
}

// ---------------- sin/cos table: double-precision provenance ----------------
__global__ void k_sincos() {
    int s = blockIdx.x, d = threadIdx.x;
    double invf_d = pow(10000.0, (double)d / 64.0);
    float invf = (float)invf_d;
    float arg = (float)s * invf;
    double a = (double)arg;
    g_sin[s*64 + d] = (float)sin(a);
    g_cos[s*64 + d] = (float)cos(a);
}

// ---------------- gamma/beta + RoPE -> split q,k ----------------
__global__ __launch_bounds__(64) void k_rope(const float* __restrict__ gamma,
                                             const float* __restrict__ beta) {
    int row = blockIdx.x;
    int s = row & (S_ - 1);
    int d = threadIdx.x;
    const float* base = g_base + (size_t)row * SD_;
    float b1 = base[d], b2 = base[d + 64];
    float sn = g_sin[s*64 + d], cs = g_cos[s*64 + d];
    float x1 = b1 * gamma[d]      + beta[d];
    float x2 = b2 * gamma[d + 64] + beta[d + 64];
    float q0 = x1*cs - x2*sn, q1 = x2*cs + x1*sn;
    float y1 = b1 * gamma[128 + d]      + beta[128 + d];
    float y2 = b2 * gamma[128 + 64 + d] + beta[128 + 64 + d];
    float k0 = y1*cs - y2*sn, k1 = y2*cs + y1*sn;
    size_t o = (size_t)row * SD_;
    fp16 h, l;
    split2(q0, h, l); g_qh[o+d] = h;    g_ql[o+d] = l;
    split2(q1, h, l); g_qh[o+d+64] = h; g_ql[o+d+64] = l;
    split2(k0, h, l); g_kh[o+d] = h;    g_kl[o+d] = l;
    split2(k1, h, l); g_kh[o+d+64] = h; g_kl[o+d+64] = l;
}

// ---------------- v transpose + split: [b][t][e] fp32 -> [b][e][t] fp16 hi/lo ----------------
__global__ __launch_bounds__(256) void k_vt() {
    __shared__ float tile[32][33];
    int e0 = blockIdx.x * 32, t0 = blockIdx.y * 32, b = blockIdx.z;
    int tx = threadIdx.x, ty = threadIdx.y;   // block (32,8)
    #pragma unroll
    for (int i = 0; i < 4; i++) {
        int t = t0 + ty + i*8;
        tile[ty + i*8][tx] = g_v[((size_t)b*S_ + t)*E_ + e0 + tx];
    }
    __syncthreads();
    #pragma unroll
    for (int i = 0; i < 4; i++) {
        int e = e0 + ty + i*8;
        float x = tile[tx][ty + i*8];
        fp16 h, l; split2(x, h, l);
        size_t o = ((size_t)b*E_ + e)*S_ + t0 + tx;
        g_vth[o] = h; g_vtl[o] = l;
    }
}

// =================================================================
// mma.sync fp16 GEMM: 128x128 CTA tile, 8 warps (4m x 2n, 32x64 each),
// BK=32 double-buffered cp.async.
// THREE=1: D += Ah*Bh + Ah*Bl + Al*Bh   (full split)
// THREE=0: D += Ah*Bh + Ah*Bl           (A single fp16)
// EPI: 0=uv  1=qk  2=pv  3=out
// =================================================================
#define KPAD   40            // fp16 elements per smem row (32 + 8 pad)
#define ARR_B  (128*KPAD*2)  // 10240 bytes per operand array
#define BUF_B  (4*ARR_B)     // 40960 per stage
#define SMEMSZ (2*BUF_B)     // 81920

template<int EPI, bool THREE>
__global__ __launch_bounds__(256) void k_gemm(const float* __restrict__ aux,
                                              const float* __restrict__ aux2,
                                              float* __restrict__ fout) {
    constexpr int LD = (EPI==0) ? 512 : (EPI==1) ? 128 : (EPI==2) ? 512 : 1024;
    constexpr int NS = LD / 32;

    extern __shared__ __align__(16) char smem[];
    const uint32_t sb = smem_u32(smem);
    const int tid = threadIdx.x, wid = tid >> 5, lane = tid & 31;
    const int bm = blockIdx.y * 128, bn = blockIdx.x * 128, bz = blockIdx.z;

    const fp16 *Ah, *Al, *Bh, *Bl;
    if (EPI == 0)      { Ah = g_xnh; Al = g_xnl; Bh = g_wh;  Bl = g_wl; }
    else if (EPI == 1) { size_t o = (size_t)bz*S_*SD_;
                         Ah = g_qh+o; Al = g_ql+o; Bh = g_kh+o; Bl = g_kl+o; }
    else if (EPI == 2) { size_t oa = (size_t)bz*S_*S_, ob = (size_t)bz*E_*S_;
                         Ah = g_p+oa; Al = g_p+oa; Bh = g_vth+ob; Bl = g_vtl+ob; }
    else               { Ah = g_gt; Al = g_gt; Bh = g_owh; Bl = g_owl; }

    const int lrow = tid >> 1;
    const int lc   = (tid & 1) * 16;
    const fp16* gAh = Ah + (size_t)(bm + lrow) * LD + lc;
    const fp16* gAl = Al + (size_t)(bm + lrow) * LD + lc;
    const fp16* gBh = Bh + (size_t)(bn + lrow) * LD + lc;
    const fp16* gBl = Bl + (size_t)(bn + lrow) * LD + lc;
    const uint32_t srow = sb + lrow * (KPAD*2) + lc * 2;

    auto load_stage = [&](int s) {
        const uint32_t d = srow + (s & 1) * BUF_B;
        const int off = s * 32;
        cpa16(d + 0*ARR_B,      gAh + off); cpa16(d + 0*ARR_B + 16, gAh + off + 8);
        if (THREE) {
            cpa16(d + 1*ARR_B,      gAl + off); cpa16(d + 1*ARR_B + 16, gAl + off + 8);
        }
        cpa16(d + 2*ARR_B,      gBh + off); cpa16(d + 2*ARR_B + 16, gBh + off + 8);
        cpa16(d + 3*ARR_B,      gBl + off); cpa16(d + 3*ARR_B + 16, gBl + off + 8);
    };

    load_stage(0); CP_COMMIT();
    load_stage(1); CP_COMMIT();

    const int am = (wid & 3) * 32;      // warp rows
    const int an = (wid >> 2) * 64;     // warp cols
    float acc[2][8][4];
    #pragma unroll
    for (int mt = 0; mt < 2; mt++)
        #pragma unroll
        for (int nt = 0; nt < 8; nt++)
            #pragma unroll
            for (int j = 0; j < 4; j++) acc[mt][nt][j] = 0.f;

    const int a_row = am + (lane & 15);
    const int a_col = (lane >> 4) * 8;
    const int b_row = an + ((lane >> 4) & 1) * 8 + (lane & 7);
    const int b_col = ((lane >> 3) & 1) * 8;

    for (int s = 0; s < NS; s++) {
        if (s + 1 < NS) { CP_WAIT(1); } else { CP_WAIT(0); }
        __syncthreads();
        const uint32_t bufb = sb + (s & 1) * BUF_B;
        #pragma unroll
        for (int kk = 0; kk < 32; kk += 16) {
            uint32_t ah[2][4], al[2][4];
            #pragma unroll
            for (int mt = 0; mt < 2; mt++) {
                uint32_t ad = bufb + (a_row + mt*16) * (KPAD*2) + (kk + a_col) * 2;
                ldm4(ah[mt], ad);
                if (THREE) ldm4(al[mt], ad + ARR_B);
            }
            uint32_t bh[8][2], bl[8][2];
            #pragma unroll
            for (int n2 = 0; n2 < 4; n2++) {
                uint32_t bd = bufb + 2*ARR_B + (b_row + n2*16) * (KPAD*2) + (kk + b_col) * 2;
                uint32_t r[4];
                ldm4(r, bd);
                bh[n2*2][0]=r[0]; bh[n2*2][1]=r[1]; bh[n2*2+1][0]=r[2]; bh[n2*2+1][1]=r[3];
                ldm4(r, bd + ARR_B);
                bl[n2*2][0]=r[0]; bl[n2*2][1]=r[1]; bl[n2*2+1][0]=r[2]; bl[n2*2+1][1]=r[3];
            }
            #pragma unroll
            for (int mt = 0; mt < 2; mt++)
                #pragma unroll
                for (int nt = 0; nt < 8; nt++) {
                    mma16816(acc[mt][nt], ah[mt], bh[nt]);
                    mma16816(acc[mt][nt], ah[mt], bl[nt]);
                    if (THREE) mma16816(acc[mt][nt], al[mt], bh[nt]);
                }
        }
        __syncthreads();
        if (s + 2 < NS) { load_stage(s + 2); CP_COMMIT(); }
    }

    // -------- epilogue --------
    const int r4 = lane >> 2, c2 = (lane & 3) * 2;
    #pragma unroll
    for (int mt = 0; mt < 2; mt++)
        #pragma unroll
        for (int half = 0; half < 2; half++) {
            const int row = bm + am + mt*16 + half*8 + r4;
            #pragma unroll
            for (int nt = 0; nt < 8; nt++) {
                const int col = bn + an + nt*8 + c2;
                float v0 = acc[mt][nt][half*2 + 0];
                float v1 = acc[mt][nt][half*2 + 1];

                if (EPI == 0) {
                    float a0 = v0 + aux[col], a1 = v1 + aux[col+1];
                    a0 = a0 / (1.0f + expf(-a0));
                    a1 = a1 / (1.0f + expf(-a1));
                    if (col < E_)
                        *(float2*)(g_u + (size_t)row*E_ + col) = make_float2(a0, a1);
                    else if (col < 2*E_)
                        *(float2*)(g_v + (size_t)row*E_ + (col - E_)) = make_float2(a0, a1);
                    else
                        *(float2*)(g_base + (size_t)row*SD_ + (col - 2*E_)) = make_float2(a0, a1);
                } else if (EPI == 1) {
                    float a0 = (v0 + aux[col     - row + (S_-1)]) / 11.313708498984761f;
                    float a1 = (v1 + aux[col + 1 - row + (S_-1)]) / 11.313708498984761f;
                    a0 = fmaxf(a0, 0.f); a1 = fmaxf(a1, 0.f);
                    a0 *= a0; a1 *= a1;
                    size_t o = (size_t)bz*S_*S_ + (size_t)row*S_ + col;
                    *(uint32_t*)(g_p + o) = packh(__float2half_rn(a0), __float2half_rn(a1));
                } else if (EPI == 2) {
                    size_t rr = (size_t)bz*S_ + row;
                    float u0 = g_u[rr*E_ + col], u1 = g_u[rr*E_ + col + 1];
                    float a0 = v0 * u0, a1 = v1 * u1;
                    *(uint32_t*)(g_gt + rr*E_ + col) = packh(__float2half_rn(a0), __float2half_rn(a1));
                } else {
                    size_t o = (size_t)row*H_ + col;
                    float a0 = v0 + aux[col]     + aux2[o];
                    float a1 = v1 + aux[col + 1] + aux2[o + 1];
                    *(float2*)(fout + o) = make_float2(a0, a1);
                }
            }
        }
}

// ---------------- launch ----------------
extern "C" void kernel_launch(void* const* d_in, const int* in_sizes, int n_in,
                              void* d_out, int out_size) {
    const float* x    = (const float*)d_in[0];
    const float* ln_g = (const float*)d_in[1];
    const float* uv_w = (const float*)d_in[2];
    const float* uv_b = (const float*)d_in[3];
    const float* gam  = (const float*)d_in[4];
    const float* bet  = (const float*)d_in[5];
    const float* wb   = (const float*)d_in[6];
    const float* o_w  = (const float*)d_in[7];
    const float* o_b  = (const float*)d_in[8];
    float* out = (float*)d_out;

    static bool attr_done = false;
    if (!attr_done) {
        cudaFuncSetAttribute(k_gemm<0,true>,  cudaFuncAttributeMaxDynamicSharedMemorySize, SMEMSZ);
        cudaFuncSetAttribute(k_gemm<1,true>,  cudaFuncAttributeMaxDynamicSharedMemorySize, SMEMSZ);
        cudaFuncSetAttribute(k_gemm<2,false>, cudaFuncAttributeMaxDynamicSharedMemorySize, SMEMSZ);
        cudaFuncSetAttribute(k_gemm<3,false>, cudaFuncAttributeMaxDynamicSharedMemorySize, SMEMSZ);
        attr_done = true;
    }

    fp16 *wh, *wl, *owh, *owl;
    cudaGetSymbolAddress((void**)&wh,  g_wh);
    cudaGetSymbolAddress((void**)&wl,  g_wl);
    cudaGetSymbolAddress((void**)&owh, g_owh);
    cudaGetSymbolAddress((void**)&owl, g_owl);

    k_norm  <<<M_, 128>>>(x, ln_g);
    k_split <<<(UV_*H_/4 + 255)/256, 256>>>(uv_w, wh, wl, UV_*H_/4);
    k_split <<<(H_*E_/4 + 255)/256, 256>>>(o_w, owh, owl, H_*E_/4);
    k_sincos<<<S_, 64>>>();

    k_gemm<0,true ><<<dim3(UV_/128, M_/128), 256, SMEMSZ>>>(uv_b, nullptr, nullptr);
    k_rope  <<<M_, 64>>>(gam, bet);
    k_vt    <<<dim3(E_/32, S_/32, B_), dim3(32, 8)>>>();
    k_gemm<1,true ><<<dim3(S_/128, S_/128, B_), 256, SMEMSZ>>>(wb, nullptr, nullptr);
    k_gemm<2,false><<<dim3(E_/128, S_/128, B_), 256, SMEMSZ>>>(nullptr, nullptr, nullptr);
    k_gemm<3,false><<<dim3(H_/128, M_/128), 256, SMEMSZ>>>(o_b, x, out);
}

// round 5
// speedup vs baseline: 2.7183x; 1.2235x over previous
#include <cuda_runtime.h>
#include <cuda_fp16.h>
#include <math.h>
#include <stdint.h>

#define B_   64
#define S_   512
#define H_   512
#define E_   1024
#define UV_  2176
#define SD_  128
#define M_   (B_*S_)

typedef __half fp16;

// ---------------- scratch (device globals) ----------------
__device__ __align__(16) fp16  g_xnh[(size_t)M_*H_];
__device__ __align__(16) fp16  g_xnl[(size_t)M_*H_];
__device__ __align__(16) fp16  g_wh [(size_t)UV_*H_];
__device__ __align__(16) fp16  g_wl [(size_t)UV_*H_];
__device__ __align__(16) fp16  g_owh[(size_t)H_*E_];
__device__ __align__(16) fp16  g_owl[(size_t)H_*E_];
__device__ __align__(16) float g_u  [(size_t)M_*E_];
__device__ __align__(16) float g_v  [(size_t)M_*E_];      // [b][t][e] fp32
__device__ __align__(16) fp16  g_vth[(size_t)B_*E_*S_];   // [b][e][t]
__device__ __align__(16) fp16  g_vtl[(size_t)B_*E_*S_];
__device__ __align__(16) float g_base[(size_t)M_*SD_];
__device__ __align__(16) fp16  g_qh[(size_t)M_*SD_];
__device__ __align__(16) fp16  g_ql[(size_t)M_*SD_];
__device__ __align__(16) fp16  g_kh[(size_t)M_*SD_];
__device__ __align__(16) fp16  g_kl[(size_t)M_*SD_];
__device__ __align__(16) fp16  g_p [(size_t)B_*S_*S_];    // scores, single fp16
__device__ __align__(16) fp16  g_gt[(size_t)M_*E_];       // gated, single fp16
__device__ float g_sin[S_*64];
__device__ float g_cos[S_*64];

// ---------------- helpers ----------------
__device__ __forceinline__ uint32_t smem_u32(const void* p) {
    uint32_t a;
    asm("{ .reg .u64 t; cvta.to.shared.u64 t, %1; cvt.u32.u64 %0, t; }" : "=r"(a) : "l"(p));
    return a;
}
__device__ __forceinline__ void cpa16(uint32_t s, const void* g) {
    asm volatile("cp.async.cg.shared.global [%0], [%1], 16;" :: "r"(s), "l"(g));
}
#define CP_COMMIT() asm volatile("cp.async.commit_group;")
#define CP_WAIT(n)  asm volatile("cp.async.wait_group %0;" :: "n"(n) : "memory")

__device__ __forceinline__ void ldm4(uint32_t* r, uint32_t a) {
    asm volatile("ldmatrix.sync.aligned.m8n8.x4.shared.b16 {%0,%1,%2,%3},[%4];"
                 : "=r"(r[0]), "=r"(r[1]), "=r"(r[2]), "=r"(r[3]) : "r"(a));
}
__device__ __forceinline__ void mma16816(float* d, const uint32_t* a, const uint32_t* b) {
    asm volatile("mma.sync.aligned.m16n8k16.row.col.f32.f16.f16.f32 "
                 "{%0,%1,%2,%3},{%4,%5,%6,%7},{%8,%9},{%0,%1,%2,%3};"
                 : "+f"(d[0]), "+f"(d[1]), "+f"(d[2]), "+f"(d[3])
                 : "r"(a[0]), "r"(a[1]), "r"(a[2]), "r"(a[3]), "r"(b[0]), "r"(b[1]));
}
__device__ __forceinline__ void split2(float x, fp16& h, fp16& l) {
    h = __float2half_rn(x);
    l = __float2half_rn(x - __half2float(h));
}
__device__ __forceinline__ uint32_t packh(fp16 a, fp16 b) {
    return (uint32_t)__half_as_ushort(a) | ((uint32_t)__half_as_ushort(b) << 16);
}

// ---------------- norm -> split fp16 ----------------
__global__ __launch_bounds__(128) void k_norm(const float* __restrict__ x,
                                              const float* __restrict__ ln_g) {
    int row = blockIdx.x;
    const float4* xr = (const float4*)(x + (size_t)row * H_);
    float4 a = xr[threadIdx.x];
    float ss = a.x*a.x + a.y*a.y + a.z*a.z + a.w*a.w;
    #pragma unroll
    for (int o = 16; o; o >>= 1) ss += __shfl_xor_sync(0xffffffffu, ss, o);
    __shared__ float ws[4];
    if ((threadIdx.x & 31) == 0) ws[threadIdx.x >> 5] = ss;
    __syncthreads();
    float total = ws[0] + ws[1] + ws[2] + ws[3];
    float norm = sqrtf(total * (1.0f / (float)H_));
    float sc = ln_g[0] / fmaxf(norm, 1e-5f);
    float v[4] = {a.x*sc, a.y*sc, a.z*sc, a.w*sc};
    fp16 h[4], l[4];
    #pragma unroll
    for (int i = 0; i < 4; i++) split2(v[i], h[i], l[i]);
    size_t off = (size_t)row * H_ + threadIdx.x * 4;
    *(uint2*)(g_xnh + off) = *(uint2*)h;
    *(uint2*)(g_xnl + off) = *(uint2*)l;
}

// ---------------- generic fp32 -> fp16 hi/lo split ----------------
__global__ __launch_bounds__(256) void k_split(const float* __restrict__ src,
                                               fp16* __restrict__ dh, fp16* __restrict__ dl,
                                               int n4) {
    int i = blockIdx.x * blockDim.x + threadIdx.x;
    if (i >= n4) return;
    float4 a = ((const float4*)src)[i];
    float v[4] = {a.x, a.y, a.z, a.w};
    fp16 h[4], l[4];
    #pragma unroll
    for (int k = 0; k < 4; k++) split2(v[k], h[k], l[k]);
    *(uint2*)(dh + (size_t)i*4) = *(uint2*)h;
    *(uint2*)(dl + (size_t)i*4) = *(uint2*)l;
}

// ---------------- sin/cos table: double-precision provenance ----------------
__global__ void k_sincos() {
    int s = blockIdx.x, d = threadIdx.x;
    double invf_d = pow(10000.0, (double)d / 64.0);
    float invf = (float)invf_d;
    float arg = (float)s * invf;
    double a = (double)arg;
    g_sin[s*64 + d] = (float)sin(a);
    g_cos[s*64 + d] = (float)cos(a);
}

// ---------------- gamma/beta + RoPE -> split q,k ----------------
__global__ __launch_bounds__(64) void k_rope(const float* __restrict__ gamma,
                                             const float* __restrict__ beta) {
    int row = blockIdx.x;
    int s = row & (S_ - 1);
    int d = threadIdx.x;
    const float* base = g_base + (size_t)row * SD_;
    float b1 = base[d], b2 = base[d + 64];
    float sn = g_sin[s*64 + d], cs = g_cos[s*64 + d];
    float x1 = b1 * gamma[d]      + beta[d];
    float x2 = b2 * gamma[d + 64] + beta[d + 64];
    float q0 = x1*cs - x2*sn, q1 = x2*cs + x1*sn;
    float y1 = b1 * gamma[128 + d]      + beta[128 + d];
    float y2 = b2 * gamma[128 + 64 + d] + beta[128 + 64 + d];
    float k0 = y1*cs - y2*sn, k1 = y2*cs + y1*sn;
    size_t o = (size_t)row * SD_;
    fp16 h, l;
    split2(q0, h, l); g_qh[o+d] = h;    g_ql[o+d] = l;
    split2(q1, h, l); g_qh[o+d+64] = h; g_ql[o+d+64] = l;
    split2(k0, h, l); g_kh[o+d] = h;    g_kl[o+d] = l;
    split2(k1, h, l); g_kh[o+d+64] = h; g_kl[o+d+64] = l;
}

// ---------------- v transpose + split: [b][t][e] fp32 -> [b][e][t] fp16 hi/lo ----------------
__global__ __launch_bounds__(256) void k_vt() {
    __shared__ float tile[32][33];
    int e0 = blockIdx.x * 32, t0 = blockIdx.y * 32, b = blockIdx.z;
    int tx = threadIdx.x, ty = threadIdx.y;   // block (32,8)
    #pragma unroll
    for (int i = 0; i < 4; i++) {
        int t = t0 + ty + i*8;
        tile[ty + i*8][tx] = g_v[((size_t)b*S_ + t)*E_ + e0 + tx];
    }
    __syncthreads();
    #pragma unroll
    for (int i = 0; i < 4; i++) {
        int e = e0 + ty + i*8;
        float x = tile[tx][ty + i*8];
        fp16 h, l; split2(x, h, l);
        size_t o = ((size_t)b*E_ + e)*S_ + t0 + tx;
        g_vth[o] = h; g_vtl[o] = l;
    }
}

// =================================================================
// mma.sync fp16 GEMM: 128x128 CTA tile, 8 warps (4m x 2n, 32x64 each),
// BK=32 double-buffered cp.async.
// three=1: D += Ah*Bh + Ah*Bl + Al*Bh   (full split)
// three=0: D += Ah*Bh + Ah*Bl           (A single fp16)
// EPI 0 (uv): per-tile runtime choice — base columns (tile 16) 3-pass,
//             u/v columns 2-pass.
// EPI: 0=uv  1=qk  2=pv  3=out
// =================================================================
#define KPAD   40            // fp16 elements per smem row (32 + 8 pad)
#define ARR_B  (128*KPAD*2)  // 10240 bytes per operand array
#define BUF_B  (4*ARR_B)     // 40960 per stage
#define SMEMSZ (2*BUF_B)     // 81920

template<int EPI, bool THREE>
__global__ __launch_bounds__(256) void k_gemm(const float* __restrict__ aux,
                                              const float* __restrict__ aux2,
                                              float* __restrict__ fout) {
    constexpr int LD = (EPI==0) ? 512 : (EPI==1) ? 128 : (EPI==2) ? 512 : 1024;
    constexpr int NS = LD / 32;

    extern __shared__ __align__(16) char smem[];
    const uint32_t sb = smem_u32(smem);
    const int tid = threadIdx.x, wid = tid >> 5, lane = tid & 31;
    const int bm = blockIdx.y * 128, bn = blockIdx.x * 128, bz = blockIdx.z;

    // EPI 0: only the base-column tile (cols 2048..2175) needs the 3rd pass.
    const bool three = (EPI == 0) ? (blockIdx.x == UV_/128 - 1) : THREE;

    const fp16 *Ah, *Al, *Bh, *Bl;
    if (EPI == 0)      { Ah = g_xnh; Al = g_xnl; Bh = g_wh;  Bl = g_wl; }
    else if (EPI == 1) { size_t o = (size_t)bz*S_*SD_;
                         Ah = g_qh+o; Al = g_ql+o; Bh = g_kh+o; Bl = g_kl+o; }
    else if (EPI == 2) { size_t oa = (size_t)bz*S_*S_, ob = (size_t)bz*E_*S_;
                         Ah = g_p+oa; Al = g_p+oa; Bh = g_vth+ob; Bl = g_vtl+ob; }
    else               { Ah = g_gt; Al = g_gt; Bh = g_owh; Bl = g_owl; }

    const int lrow = tid >> 1;
    const int lc   = (tid & 1) * 16;
    const fp16* gAh = Ah + (size_t)(bm + lrow) * LD + lc;
    const fp16* gAl = Al + (size_t)(bm + lrow) * LD + lc;
    const fp16* gBh = Bh + (size_t)(bn + lrow) * LD + lc;
    const fp16* gBl = Bl + (size_t)(bn + lrow) * LD + lc;
    const uint32_t srow = sb + lrow * (KPAD*2) + lc * 2;

    auto load_stage = [&](int s) {
        const uint32_t d = srow + (s & 1) * BUF_B;
        const int off = s * 32;
        cpa16(d + 0*ARR_B,      gAh + off); cpa16(d + 0*ARR_B + 16, gAh + off + 8);
        if (three) {
            cpa16(d + 1*ARR_B,      gAl + off); cpa16(d + 1*ARR_B + 16, gAl + off + 8);
        }
        cpa16(d + 2*ARR_B,      gBh + off); cpa16(d + 2*ARR_B + 16, gBh + off + 8);
        cpa16(d + 3*ARR_B,      gBl + off); cpa16(d + 3*ARR_B + 16, gBl + off + 8);
    };

    load_stage(0); CP_COMMIT();
    load_stage(1); CP_COMMIT();

    const int am = (wid & 3) * 32;      // warp rows
    const int an = (wid >> 2) * 64;     // warp cols
    float acc[2][8][4];
    #pragma unroll
    for (int mt = 0; mt < 2; mt++)
        #pragma unroll
        for (int nt = 0; nt < 8; nt++)
            #pragma unroll
            for (int j = 0; j < 4; j++) acc[mt][nt][j] = 0.f;

    const int a_row = am + (lane & 15);
    const int a_col = (lane >> 4) * 8;
    const int b_row = an + ((lane >> 4) & 1) * 8 + (lane & 7);
    const int b_col = ((lane >> 3) & 1) * 8;

    for (int s = 0; s < NS; s++) {
        if (s + 1 < NS) { CP_WAIT(1); } else { CP_WAIT(0); }
        __syncthreads();
        const uint32_t bufb = sb + (s & 1) * BUF_B;
        #pragma unroll
        for (int kk = 0; kk < 32; kk += 16) {
            uint32_t ah[2][4], al[2][4];
            #pragma unroll
            for (int mt = 0; mt < 2; mt++) {
                uint32_t ad = bufb + (a_row + mt*16) * (KPAD*2) + (kk + a_col) * 2;
                ldm4(ah[mt], ad);
                if (three) ldm4(al[mt], ad + ARR_B);
            }
            uint32_t bh[8][2], bl[8][2];
            #pragma unroll
            for (int n2 = 0; n2 < 4; n2++) {
                uint32_t bd = bufb + 2*ARR_B + (b_row + n2*16) * (KPAD*2) + (kk + b_col) * 2;
                uint32_t r[4];
                ldm4(r, bd);
                bh[n2*2][0]=r[0]; bh[n2*2][1]=r[1]; bh[n2*2+1][0]=r[2]; bh[n2*2+1][1]=r[3];
                ldm4(r, bd + ARR_B);
                bl[n2*2][0]=r[0]; bl[n2*2][1]=r[1]; bl[n2*2+1][0]=r[2]; bl[n2*2+1][1]=r[3];
            }
            #pragma unroll
            for (int mt = 0; mt < 2; mt++)
                #pragma unroll
                for (int nt = 0; nt < 8; nt++) {
                    mma16816(acc[mt][nt], ah[mt], bh[nt]);
                    mma16816(acc[mt][nt], ah[mt], bl[nt]);
                    if (three) mma16816(acc[mt][nt], al[mt], bh[nt]);
                }
        }
        __syncthreads();
        if (s + 2 < NS) { load_stage(s + 2); CP_COMMIT(); }
    }

    // -------- epilogue --------
    const int r4 = lane >> 2, c2 = (lane & 3) * 2;
    #pragma unroll
    for (int mt = 0; mt < 2; mt++)
        #pragma unroll
        for (int half = 0; half < 2; half++) {
            const int row = bm + am + mt*16 + half*8 + r4;
            #pragma unroll
            for (int nt = 0; nt < 8; nt++) {
                const int col = bn + an + nt*8 + c2;
                float v0 = acc[mt][nt][half*2 + 0];
                float v1 = acc[mt][nt][half*2 + 1];

                if (EPI == 0) {
                    float a0 = v0 + aux[col], a1 = v1 + aux[col+1];
                    a0 = a0 / (1.0f + expf(-a0));
                    a1 = a1 / (1.0f + expf(-a1));
                    if (col < E_)
                        *(float2*)(g_u + (size_t)row*E_ + col) = make_float2(a0, a1);
                    else if (col < 2*E_)
                        *(float2*)(g_v + (size_t)row*E_ + (col - E_)) = make_float2(a0, a1);
                    else
                        *(float2*)(g_base + (size_t)row*SD_ + (col - 2*E_)) = make_float2(a0, a1);
                } else if (EPI == 1) {
                    float a0 = (v0 + aux[col     - row + (S_-1)]) / 11.313708498984761f;
                    float a1 = (v1 + aux[col + 1 - row + (S_-1)]) / 11.313708498984761f;
                    a0 = fmaxf(a0, 0.f); a1 = fmaxf(a1, 0.f);
                    a0 *= a0; a1 *= a1;
                    size_t o = (size_t)bz*S_*S_ + (size_t)row*S_ + col;
                    *(uint32_t*)(g_p + o) = packh(__float2half_rn(a0), __float2half_rn(a1));
                } else if (EPI == 2) {
                    size_t rr = (size_t)bz*S_ + row;
                    float u0 = g_u[rr*E_ + col], u1 = g_u[rr*E_ + col + 1];
                    float a0 = v0 * u0, a1 = v1 * u1;
                    *(uint32_t*)(g_gt + rr*E_ + col) = packh(__float2half_rn(a0), __float2half_rn(a1));
                } else {
                    size_t o = (size_t)row*H_ + col;
                    float a0 = v0 + aux[col]     + aux2[o];
                    float a1 = v1 + aux[col + 1] + aux2[o + 1];
                    *(float2*)(fout + o) = make_float2(a0, a1);
                }
            }
        }
}

// ---------------- launch ----------------
extern "C" void kernel_launch(void* const* d_in, const int* in_sizes, int n_in,
                              void* d_out, int out_size) {
    const float* x    = (const float*)d_in[0];
    const float* ln_g = (const float*)d_in[1];
    const float* uv_w = (const float*)d_in[2];
    const float* uv_b = (const float*)d_in[3];
    const float* gam  = (const float*)d_in[4];
    const float* bet  = (const float*)d_in[5];
    const float* wb   = (const float*)d_in[6];
    const float* o_w  = (const float*)d_in[7];
    const float* o_b  = (const float*)d_in[8];
    float* out = (float*)d_out;

    static bool attr_done = false;
    if (!attr_done) {
        cudaFuncSetAttribute(k_gemm<0,true>,  cudaFuncAttributeMaxDynamicSharedMemorySize, SMEMSZ);
        cudaFuncSetAttribute(k_gemm<1,true>,  cudaFuncAttributeMaxDynamicSharedMemorySize, SMEMSZ);
        cudaFuncSetAttribute(k_gemm<2,false>, cudaFuncAttributeMaxDynamicSharedMemorySize, SMEMSZ);
        cudaFuncSetAttribute(k_gemm<3,false>, cudaFuncAttributeMaxDynamicSharedMemorySize, SMEMSZ);
        attr_done = true;
    }

    fp16 *wh, *wl, *owh, *owl;
    cudaGetSymbolAddress((void**)&wh,  g_wh);
    cudaGetSymbolAddress((void**)&wl,  g_wl);
    cudaGetSymbolAddress((void**)&owh, g_owh);
    cudaGetSymbolAddress((void**)&owl, g_owl);

    k_norm  <<<M_, 128>>>(x, ln_g);
    k_split <<<(UV_*H_/4 + 255)/256, 256>>>(uv_w, wh, wl, UV_*H_/4);
    k_split <<<(H_*E_/4 + 255)/256, 256>>>(o_w, owh, owl, H_*E_/4);
    k_sincos<<<S_, 64>>>();

    k_gemm<0,true ><<<dim3(UV_/128, M_/128), 256, SMEMSZ>>>(uv_b, nullptr, nullptr);
    k_rope  <<<M_, 64>>>(gam, bet);
    k_vt    <<<dim3(E_/32, S_/32, B_), dim3(32, 8)>>>();
    k_gemm<1,true ><<<dim3(S_/128, S_/128, B_), 256, SMEMSZ>>>(wb, nullptr, nullptr);
    k_gemm<2,false><<<dim3(E_/128, S_/128, B_), 256, SMEMSZ>>>(nullptr, nullptr, nullptr);
    k_gemm<3,false><<<dim3(H_/128, M_/128), 256, SMEMSZ>>>(o_b, x, out);
}

// round 6
// speedup vs baseline: 3.6347x; 1.3371x over previous
#include <cuda_runtime.h>
#include <cuda_fp16.h>
#include <math.h>
#include <stdint.h>

#define B_   64
#define S_   512
#define H_   512
#define E_   1024
#define UV_  2176
#define SD_  128
#define M_   (B_*S_)

typedef __half fp16;

// ---------------- scratch (device globals) ----------------
__device__ __align__(16) fp16  g_xnh[(size_t)M_*H_];
__device__ __align__(16) fp16  g_xnl[(size_t)M_*H_];
__device__ __align__(16) fp16  g_wh [(size_t)UV_*H_];
__device__ __align__(16) fp16  g_wl [(size_t)UV_*H_];
__device__ __align__(16) fp16  g_owh[(size_t)H_*E_];
__device__ __align__(16) fp16  g_owl[(size_t)H_*E_];
__device__ __align__(16) float g_u  [(size_t)M_*E_];
__device__ __align__(16) float g_v  [(size_t)M_*E_];      // [b][t][e] fp32
__device__ __align__(16) fp16  g_vth[(size_t)B_*E_*S_];   // [b][e][t]
__device__ __align__(16) float g_base[(size_t)M_*SD_];
__device__ __align__(16) fp16  g_qh[(size_t)M_*SD_];
__device__ __align__(16) fp16  g_ql[(size_t)M_*SD_];
__device__ __align__(16) fp16  g_kh[(size_t)M_*SD_];
__device__ __align__(16) fp16  g_kl[(size_t)M_*SD_];
__device__ __align__(16) fp16  g_p [(size_t)B_*S_*S_];    // scores, single fp16
__device__ __align__(16) fp16  g_gt[(size_t)M_*E_];       // gated, single fp16
__device__ float g_sin[S_*64];
__device__ float g_cos[S_*64];

// ---------------- helpers ----------------
__device__ __forceinline__ uint32_t smem_u32(const void* p) {
    uint32_t a;
    asm("{ .reg .u64 t; cvta.to.shared.u64 t, %1; cvt.u32.u64 %0, t; }" : "=r"(a) : "l"(p));
    return a;
}
__device__ __forceinline__ void cpa16(uint32_t s, const void* g) {
    asm volatile("cp.async.cg.shared.global [%0], [%1], 16;" :: "r"(s), "l"(g));
}
#define CP_COMMIT() asm volatile("cp.async.commit_group;")
#define CP_WAIT(n)  asm volatile("cp.async.wait_group %0;" :: "n"(n) : "memory")

__device__ __forceinline__ void ldm4(uint32_t* r, uint32_t a) {
    asm volatile("ldmatrix.sync.aligned.m8n8.x4.shared.b16 {%0,%1,%2,%3},[%4];"
                 : "=r"(r[0]), "=r"(r[1]), "=r"(r[2]), "=r"(r[3]) : "r"(a));
}
__device__ __forceinline__ void mma16816(float* d, const uint32_t* a, const uint32_t* b) {
    asm volatile("mma.sync.aligned.m16n8k16.row.col.f32.f16.f16.f32 "
                 "{%0,%1,%2,%3},{%4,%5,%6,%7},{%8,%9},{%0,%1,%2,%3};"
                 : "+f"(d[0]), "+f"(d[1]), "+f"(d[2]), "+f"(d[3])
                 : "r"(a[0]), "r"(a[1]), "r"(a[2]), "r"(a[3]), "r"(b[0]), "r"(b[1]));
}
__device__ __forceinline__ void split2(float x, fp16& h, fp16& l) {
    h = __float2half_rn(x);
    l = __float2half_rn(x - __half2float(h));
}
__device__ __forceinline__ uint32_t packh(fp16 a, fp16 b) {
    return (uint32_t)__half_as_ushort(a) | ((uint32_t)__half_as_ushort(b) << 16);
}

// ---------------- norm -> split fp16 ----------------
__global__ __launch_bounds__(128) void k_norm(const float* __restrict__ x,
                                              const float* __restrict__ ln_g) {
    int row = blockIdx.x;
    const float4* xr = (const float4*)(x + (size_t)row * H_);
    float4 a = xr[threadIdx.x];
    float ss = a.x*a.x + a.y*a.y + a.z*a.z + a.w*a.w;
    #pragma unroll
    for (int o = 16; o; o >>= 1) ss += __shfl_xor_sync(0xffffffffu, ss, o);
    __shared__ float ws[4];
    if ((threadIdx.x & 31) == 0) ws[threadIdx.x >> 5] = ss;
    __syncthreads();
    float total = ws[0] + ws[1] + ws[2] + ws[3];
    float norm = sqrtf(total * (1.0f / (float)H_));
    float sc = ln_g[0] / fmaxf(norm, 1e-5f);
    float v[4] = {a.x*sc, a.y*sc, a.z*sc, a.w*sc};
    fp16 h[4], l[4];
    #pragma unroll
    for (int i = 0; i < 4; i++) split2(v[i], h[i], l[i]);
    size_t off = (size_t)row * H_ + threadIdx.x * 4;
    *(uint2*)(g_xnh + off) = *(uint2*)h;
    *(uint2*)(g_xnl + off) = *(uint2*)l;
}

// ---------------- generic fp32 -> fp16 hi/lo split ----------------
__global__ __launch_bounds__(256) void k_split(const float* __restrict__ src,
                                               fp16* __restrict__ dh, fp16* __restrict__ dl,
                                               int n4) {
    int i = blockIdx.x * blockDim.x + threadIdx.x;
    if (i >= n4) return;
    float4 a = ((const float4*)src)[i];
    float v[4] = {a.x, a.y, a.z, a.w};
    fp16 h[4], l[4];
    #pragma unroll
    for (int k = 0; k < 4; k++) split2(v[k], h[k], l[k]);
    *(uint2*)(dh + (size_t)i*4) = *(uint2*)h;
    *(uint2*)(dl + (size_t)i*4) = *(uint2*)l;
}

// ---------------- sin/cos table: double-precision provenance ----------------
__global__ void k_sincos() {
    int s = blockIdx.x, d = threadIdx.x;
    double invf_d = pow(10000.0, (double)d / 64.0);
    float invf = (float)invf_d;
    float arg = (float)s * invf;
    double a = (double)arg;
    g_sin[s*64 + d] = (float)sin(a);
    g_cos[s*64 + d] = (float)cos(a);
}

// ---------------- gamma/beta + RoPE -> split q,k ----------------
__global__ __launch_bounds__(64) void k_rope(const float* __restrict__ gamma,
                                             const float* __restrict__ beta) {
    int row = blockIdx.x;
    int s = row & (S_ - 1);
    int d = threadIdx.x;
    const float* base = g_base + (size_t)row * SD_;
    float b1 = base[d], b2 = base[d + 64];
    float sn = g_sin[s*64 + d], cs = g_cos[s*64 + d];
    float x1 = b1 * gamma[d]      + beta[d];
    float x2 = b2 * gamma[d + 64] + beta[d + 64];
    float q0 = x1*cs - x2*sn, q1 = x2*cs + x1*sn;
    float y1 = b1 * gamma[128 + d]      + beta[128 + d];
    float y2 = b2 * gamma[128 + 64 + d] + beta[128 + 64 + d];
    float k0 = y1*cs - y2*sn, k1 = y2*cs + y1*sn;
    size_t o = (size_t)row * SD_;
    fp16 h, l;
    split2(q0, h, l); g_qh[o+d] = h;    g_ql[o+d] = l;
    split2(q1, h, l); g_qh[o+d+64] = h; g_ql[o+d+64] = l;
    split2(k0, h, l); g_kh[o+d] = h;    g_kl[o+d] = l;
    split2(k1, h, l); g_kh[o+d+64] = h; g_kl[o+d+64] = l;
}

// ---------------- v transpose: [b][t][e] fp32 -> [b][e][t] fp16 (hi only) ----------------
__global__ __launch_bounds__(256) void k_vt() {
    __shared__ float tile[32][33];
    int e0 = blockIdx.x * 32, t0 = blockIdx.y * 32, b = blockIdx.z;
    int tx = threadIdx.x, ty = threadIdx.y;   // block (32,8)
    #pragma unroll
    for (int i = 0; i < 4; i++) {
        int t = t0 + ty + i*8;
        tile[ty + i*8][tx] = g_v[((size_t)b*S_ + t)*E_ + e0 + tx];
    }
    __syncthreads();
    #pragma unroll
    for (int i = 0; i < 4; i++) {
        int e = e0 + ty + i*8;
        float x = tile[tx][ty + i*8];
        size_t o = ((size_t)b*E_ + e)*S_ + t0 + tx;
        g_vth[o] = __float2half_rn(x);
    }
}

// =================================================================
// mma.sync fp16 GEMM: 128x128 CTA tile, 8 warps (4m x 2n, 32x64 each),
// BK=32 double-buffered cp.async.
// MODE 1: D = Ah*Bh                     (single pass)
// MODE 2: D = Ah*Bh + Ah*Bl             (B split)
// MODE 3: D = Ah*Bh + Ah*Bl + Al*Bh     (full split)
// EPI: 0=uv  1=qk  2=pv  3=out
// bn0: column-tile offset (lets uv run two grids with different MODE)
// =================================================================
#define KPAD   40            // fp16 elements per smem row (32 + 8 pad)
#define ARR_B  (128*KPAD*2)  // 10240 bytes per operand array
#define BUF_B  (4*ARR_B)     // 40960 per stage
#define SMEMSZ (2*BUF_B)     // 81920

template<int EPI, int MODE>
__global__ __launch_bounds__(256) void k_gemm(const float* __restrict__ aux,
                                              const float* __restrict__ aux2,
                                              float* __restrict__ fout,
                                              int bn0) {
    constexpr int LD = (EPI==0) ? 512 : (EPI==1) ? 128 : (EPI==2) ? 512 : 1024;
    constexpr int NS = LD / 32;
    constexpr bool BLO   = (MODE >= 2);
    constexpr bool THREE = (MODE >= 3);

    extern __shared__ __align__(16) char smem[];
    const uint32_t sb = smem_u32(smem);
    const int tid = threadIdx.x, wid = tid >> 5, lane = tid & 31;
    const int bm = blockIdx.y * 128, bn = bn0 + blockIdx.x * 128, bz = blockIdx.z;

    const fp16 *Ah, *Al, *Bh, *Bl;
    if (EPI == 0)      { Ah = g_xnh; Al = g_xnl; Bh = g_wh;  Bl = g_wl; }
    else if (EPI == 1) { size_t o = (size_t)bz*S_*SD_;
                         Ah = g_qh+o; Al = g_ql+o; Bh = g_kh+o; Bl = g_kl+o; }
    else if (EPI == 2) { size_t oa = (size_t)bz*S_*S_, ob = (size_t)bz*E_*S_;
                         Ah = g_p+oa; Al = g_p+oa; Bh = g_vth+ob; Bl = g_vth+ob; }
    else               { Ah = g_gt; Al = g_gt; Bh = g_owh; Bl = g_owl; }

    const int lrow = tid >> 1;
    const int lc   = (tid & 1) * 16;
    const fp16* gAh = Ah + (size_t)(bm + lrow) * LD + lc;
    const fp16* gAl = Al + (size_t)(bm + lrow) * LD + lc;
    const fp16* gBh = Bh + (size_t)(bn + lrow) * LD + lc;
    const fp16* gBl = Bl + (size_t)(bn + lrow) * LD + lc;
    const uint32_t srow = sb + lrow * (KPAD*2) + lc * 2;

    auto load_stage = [&](int s) {
        const uint32_t d = srow + (s & 1) * BUF_B;
        const int off = s * 32;
        cpa16(d + 0*ARR_B,      gAh + off); cpa16(d + 0*ARR_B + 16, gAh + off + 8);
        if (THREE) {
            cpa16(d + 1*ARR_B,      gAl + off); cpa16(d + 1*ARR_B + 16, gAl + off + 8);
        }
        cpa16(d + 2*ARR_B,      gBh + off); cpa16(d + 2*ARR_B + 16, gBh + off + 8);
        if (BLO) {
            cpa16(d + 3*ARR_B,      gBl + off); cpa16(d + 3*ARR_B + 16, gBl + off + 8);
        }
    };

    load_stage(0); CP_COMMIT();
    load_stage(1); CP_COMMIT();

    const int am = (wid & 3) * 32;      // warp rows
    const int an = (wid >> 2) * 64;     // warp cols
    float acc[2][8][4];
    #pragma unroll
    for (int mt = 0; mt < 2; mt++)
        #pragma unroll
        for (int nt = 0; nt < 8; nt++)
            #pragma unroll
            for (int j = 0; j < 4; j++) acc[mt][nt][j] = 0.f;

    const int a_row = am + (lane & 15);
    const int a_col = (lane >> 4) * 8;
    const int b_row = an + ((lane >> 4) & 1) * 8 + (lane & 7);
    const int b_col = ((lane >> 3) & 1) * 8;

    for (int s = 0; s < NS; s++) {
        if (s + 1 < NS) { CP_WAIT(1); } else { CP_WAIT(0); }
        __syncthreads();
        const uint32_t bufb = sb + (s & 1) * BUF_B;
        #pragma unroll
        for (int kk = 0; kk < 32; kk += 16) {
            uint32_t ah[2][4], al[2][4];
            #pragma unroll
            for (int mt = 0; mt < 2; mt++) {
                uint32_t ad = bufb + (a_row + mt*16) * (KPAD*2) + (kk + a_col) * 2;
                ldm4(ah[mt], ad);
                if (THREE) ldm4(al[mt], ad + ARR_B);
            }
            uint32_t bh[8][2], bl[8][2];
            #pragma unroll
            for (int n2 = 0; n2 < 4; n2++) {
                uint32_t bd = bufb + 2*ARR_B + (b_row + n2*16) * (KPAD*2) + (kk + b_col) * 2;
                uint32_t r[4];
                ldm4(r, bd);
                bh[n2*2][0]=r[0]; bh[n2*2][1]=r[1]; bh[n2*2+1][0]=r[2]; bh[n2*2+1][1]=r[3];
                if (BLO) {
                    ldm4(r, bd + ARR_B);
                    bl[n2*2][0]=r[0]; bl[n2*2][1]=r[1]; bl[n2*2+1][0]=r[2]; bl[n2*2+1][1]=r[3];
                }
            }
            #pragma unroll
            for (int mt = 0; mt < 2; mt++)
                #pragma unroll
                for (int nt = 0; nt < 8; nt++) {
                    mma16816(acc[mt][nt], ah[mt], bh[nt]);
                    if (BLO)   mma16816(acc[mt][nt], ah[mt], bl[nt]);
                    if (THREE) mma16816(acc[mt][nt], al[mt], bh[nt]);
                }
        }
        __syncthreads();
        if (s + 2 < NS) { load_stage(s + 2); CP_COMMIT(); }
    }

    // -------- epilogue --------
    const int r4 = lane >> 2, c2 = (lane & 3) * 2;
    #pragma unroll
    for (int mt = 0; mt < 2; mt++)
        #pragma unroll
        for (int half = 0; half < 2; half++) {
            const int row = bm + am + mt*16 + half*8 + r4;
            #pragma unroll
            for (int nt = 0; nt < 8; nt++) {
                const int col = bn + an + nt*8 + c2;
                float v0 = acc[mt][nt][half*2 + 0];
                float v1 = acc[mt][nt][half*2 + 1];

                if (EPI == 0) {
                    float a0 = v0 + aux[col], a1 = v1 + aux[col+1];
                    a0 = a0 / (1.0f + expf(-a0));
                    a1 = a1 / (1.0f + expf(-a1));
                    if (col < E_)
                        *(float2*)(g_u + (size_t)row*E_ + col) = make_float2(a0, a1);
                    else if (col < 2*E_)
                        *(float2*)(g_v + (size_t)row*E_ + (col - E_)) = make_float2(a0, a1);
                    else
                        *(float2*)(g_base + (size_t)row*SD_ + (col - 2*E_)) = make_float2(a0, a1);
                } else if (EPI == 1) {
                    float a0 = (v0 + aux[col     - row + (S_-1)]) / 11.313708498984761f;
                    float a1 = (v1 + aux[col + 1 - row + (S_-1)]) / 11.313708498984761f;
                    a0 = fmaxf(a0, 0.f); a1 = fmaxf(a1, 0.f);
                    a0 *= a0; a1 *= a1;
                    size_t o = (size_t)bz*S_*S_ + (size_t)row*S_ + col;
                    *(uint32_t*)(g_p + o) = packh(__float2half_rn(a0), __float2half_rn(a1));
                } else if (EPI == 2) {
                    size_t rr = (size_t)bz*S_ + row;
                    float u0 = g_u[rr*E_ + col], u1 = g_u[rr*E_ + col + 1];
                    float a0 = v0 * u0, a1 = v1 * u1;
                    *(uint32_t*)(g_gt + rr*E_ + col) = packh(__float2half_rn(a0), __float2half_rn(a1));
                } else {
                    size_t o = (size_t)row*H_ + col;
                    float a0 = v0 + aux[col]     + aux2[o];
                    float a1 = v1 + aux[col + 1] + aux2[o + 1];
                    *(float2*)(fout + o) = make_float2(a0, a1);
                }
            }
        }
}

// ---------------- launch ----------------
extern "C" void kernel_launch(void* const* d_in, const int* in_sizes, int n_in,
                              void* d_out, int out_size) {
    const float* x    = (const float*)d_in[0];
    const float* ln_g = (const float*)d_in[1];
    const float* uv_w = (const float*)d_in[2];
    const float* uv_b = (const float*)d_in[3];
    const float* gam  = (const float*)d_in[4];
    const float* bet  = (const float*)d_in[5];
    const float* wb   = (const float*)d_in[6];
    const float* o_w  = (const float*)d_in[7];
    const float* o_b  = (const float*)d_in[8];
    float* out = (float*)d_out;

    static bool attr_done = false;
    if (!attr_done) {
        cudaFuncSetAttribute(k_gemm<0,1>, cudaFuncAttributeMaxDynamicSharedMemorySize, SMEMSZ);
        cudaFuncSetAttribute(k_gemm<0,3>, cudaFuncAttributeMaxDynamicSharedMemorySize, SMEMSZ);
        cudaFuncSetAttribute(k_gemm<1,3>, cudaFuncAttributeMaxDynamicSharedMemorySize, SMEMSZ);
        cudaFuncSetAttribute(k_gemm<2,1>, cudaFuncAttributeMaxDynamicSharedMemorySize, SMEMSZ);
        cudaFuncSetAttribute(k_gemm<3,2>, cudaFuncAttributeMaxDynamicSharedMemorySize, SMEMSZ);
        attr_done = true;
    }

    fp16 *wh, *wl, *owh, *owl;
    cudaGetSymbolAddress((void**)&wh,  g_wh);
    cudaGetSymbolAddress((void**)&wl,  g_wl);
    cudaGetSymbolAddress((void**)&owh, g_owh);
    cudaGetSymbolAddress((void**)&owl, g_owl);

    k_norm  <<<M_, 128>>>(x, ln_g);
    k_split <<<(UV_*H_/4 + 255)/256, 256>>>(uv_w, wh, wl, UV_*H_/4);
    k_split <<<(H_*E_/4 + 255)/256, 256>>>(o_w, owh, owl, H_*E_/4);
    k_sincos<<<S_, 64>>>();

    // uv: u/v columns 1-pass, base columns 3-pass
    k_gemm<0,1><<<dim3(16, M_/128), 256, SMEMSZ>>>(uv_b, nullptr, nullptr, 0);
    k_gemm<0,3><<<dim3(1,  M_/128), 256, SMEMSZ>>>(uv_b, nullptr, nullptr, 2048);
    k_rope  <<<M_, 64>>>(gam, bet);
    k_vt    <<<dim3(E_/32, S_/32, B_), dim3(32, 8)>>>();
    k_gemm<1,3><<<dim3(S_/128, S_/128, B_), 256, SMEMSZ>>>(wb, nullptr, nullptr, 0);
    k_gemm<2,1><<<dim3(E_/128, S_/128, B_), 256, SMEMSZ>>>(nullptr, nullptr, nullptr, 0);
    k_gemm<3,2><<<dim3(H_/128, M_/128), 256, SMEMSZ>>>(o_b, x, out, 0);
}

// round 7
// speedup vs baseline: 4.0882x; 1.1248x over previous
#include <cuda_runtime.h>
#include <cuda_fp16.h>
#include <math.h>
#include <stdint.h>

#define B_   64
#define S_   512
#define H_   512
#define E_   1024
#define UV_  2176
#define SD_  128
#define M_   (B_*S_)

typedef __half fp16;

// ---------------- scratch (device globals) ----------------
__device__ __align__(16) fp16  g_xnh[(size_t)M_*H_];
__device__ __align__(16) fp16  g_xnl[(size_t)M_*H_];
__device__ __align__(16) fp16  g_wh [(size_t)UV_*H_];
__device__ __align__(16) fp16  g_wl [(size_t)UV_*H_];
__device__ __align__(16) fp16  g_owh[(size_t)H_*E_];
__device__ __align__(16) fp16  g_uh [(size_t)M_*E_];      // u, fp16
__device__ __align__(16) fp16  g_vh [(size_t)M_*E_];      // v [b][t][e], fp16
__device__ __align__(16) fp16  g_vth[(size_t)B_*E_*S_];   // v [b][e][t], fp16
__device__ __align__(16) float g_base[(size_t)M_*SD_];
__device__ __align__(16) fp16  g_qh[(size_t)M_*SD_];
__device__ __align__(16) fp16  g_ql[(size_t)M_*SD_];
__device__ __align__(16) fp16  g_kh[(size_t)M_*SD_];
__device__ __align__(16) fp16  g_kl[(size_t)M_*SD_];
__device__ __align__(16) fp16  g_p [(size_t)B_*S_*S_];    // scores, fp16
__device__ __align__(16) fp16  g_gt[(size_t)M_*E_];       // gated, fp16
__device__ float g_sin[S_*64];
__device__ float g_cos[S_*64];

// ---------------- helpers ----------------
__device__ __forceinline__ uint32_t smem_u32(const void* p) {
    uint32_t a;
    asm("{ .reg .u64 t; cvta.to.shared.u64 t, %1; cvt.u32.u64 %0, t; }" : "=r"(a) : "l"(p));
    return a;
}
__device__ __forceinline__ void cpa16(uint32_t s, const void* g) {
    asm volatile("cp.async.cg.shared.global [%0], [%1], 16;" :: "r"(s), "l"(g));
}
#define CP_COMMIT() asm volatile("cp.async.commit_group;")
#define CP_WAIT(n)  asm volatile("cp.async.wait_group %0;" :: "n"(n) : "memory")

__device__ __forceinline__ void ldm4(uint32_t* r, uint32_t a) {
    asm volatile("ldmatrix.sync.aligned.m8n8.x4.shared.b16 {%0,%1,%2,%3},[%4];"
                 : "=r"(r[0]), "=r"(r[1]), "=r"(r[2]), "=r"(r[3]) : "r"(a));
}
__device__ __forceinline__ void mma16816(float* d, const uint32_t* a, const uint32_t* b) {
    asm volatile("mma.sync.aligned.m16n8k16.row.col.f32.f16.f16.f32 "
                 "{%0,%1,%2,%3},{%4,%5,%6,%7},{%8,%9},{%0,%1,%2,%3};"
                 : "+f"(d[0]), "+f"(d[1]), "+f"(d[2]), "+f"(d[3])
                 : "r"(a[0]), "r"(a[1]), "r"(a[2]), "r"(a[3]), "r"(b[0]), "r"(b[1]));
}
__device__ __forceinline__ void split2(float x, fp16& h, fp16& l) {
    h = __float2half_rn(x);
    l = __float2half_rn(x - __half2float(h));
}
__device__ __forceinline__ uint32_t packh(fp16 a, fp16 b) {
    return (uint32_t)__half_as_ushort(a) | ((uint32_t)__half_as_ushort(b) << 16);
}

// ---------------- norm -> split fp16 ----------------
__global__ __launch_bounds__(128) void k_norm(const float* __restrict__ x,
                                              const float* __restrict__ ln_g) {
    int row = blockIdx.x;
    const float4* xr = (const float4*)(x + (size_t)row * H_);
    float4 a = xr[threadIdx.x];
    float ss = a.x*a.x + a.y*a.y + a.z*a.z + a.w*a.w;
    #pragma unroll
    for (int o = 16; o; o >>= 1) ss += __shfl_xor_sync(0xffffffffu, ss, o);
    __shared__ float ws[4];
    if ((threadIdx.x & 31) == 0) ws[threadIdx.x >> 5] = ss;
    __syncthreads();
    float total = ws[0] + ws[1] + ws[2] + ws[3];
    float norm = sqrtf(total * (1.0f / (float)H_));
    float sc = ln_g[0] / fmaxf(norm, 1e-5f);
    float v[4] = {a.x*sc, a.y*sc, a.z*sc, a.w*sc};
    fp16 h[4], l[4];
    #pragma unroll
    for (int i = 0; i < 4; i++) split2(v[i], h[i], l[i]);
    size_t off = (size_t)row * H_ + threadIdx.x * 4;
    *(uint2*)(g_xnh + off) = *(uint2*)h;
    *(uint2*)(g_xnl + off) = *(uint2*)l;
}

// ---------------- generic fp32 -> fp16 hi/lo split ----------------
__global__ __launch_bounds__(256) void k_split(const float* __restrict__ src,
                                               fp16* __restrict__ dh, fp16* __restrict__ dl,
                                               int n4) {
    int i = blockIdx.x * blockDim.x + threadIdx.x;
    if (i >= n4) return;
    float4 a = ((const float4*)src)[i];
    float v[4] = {a.x, a.y, a.z, a.w};
    fp16 h[4], l[4];
    #pragma unroll
    for (int k = 0; k < 4; k++) split2(v[k], h[k], l[k]);
    *(uint2*)(dh + (size_t)i*4) = *(uint2*)h;
    if (dl) *(uint2*)(dl + (size_t)i*4) = *(uint2*)l;
}

// ---------------- sin/cos table: double-precision provenance ----------------
__global__ void k_sincos() {
    int s = blockIdx.x, d = threadIdx.x;
    double invf_d = pow(10000.0, (double)d / 64.0);
    float invf = (float)invf_d;
    float arg = (float)s * invf;
    double a = (double)arg;
    g_sin[s*64 + d] = (float)sin(a);
    g_cos[s*64 + d] = (float)cos(a);
}

// ---------------- gamma/beta + RoPE -> split q,k ----------------
__global__ __launch_bounds__(64) void k_rope(const float* __restrict__ gamma,
                                             const float* __restrict__ beta) {
    int row = blockIdx.x;
    int s = row & (S_ - 1);
    int d = threadIdx.x;
    const float* base = g_base + (size_t)row * SD_;
    float b1 = base[d], b2 = base[d + 64];
    float sn = g_sin[s*64 + d], cs = g_cos[s*64 + d];
    float x1 = b1 * gamma[d]      + beta[d];
    float x2 = b2 * gamma[d + 64] + beta[d + 64];
    float q0 = x1*cs - x2*sn, q1 = x2*cs + x1*sn;
    float y1 = b1 * gamma[128 + d]      + beta[128 + d];
    float y2 = b2 * gamma[128 + 64 + d] + beta[128 + 64 + d];
    float k0 = y1*cs - y2*sn, k1 = y2*cs + y1*sn;
    size_t o = (size_t)row * SD_;
    fp16 h, l;
    split2(q0, h, l); g_qh[o+d] = h;    g_ql[o+d] = l;
    split2(q1, h, l); g_qh[o+d+64] = h; g_ql[o+d+64] = l;
    split2(k0, h, l); g_kh[o+d] = h;    g_kl[o+d] = l;
    split2(k1, h, l); g_kh[o+d+64] = h; g_kl[o+d+64] = l;
}

// ---------------- v transpose: [b][t][e] fp16 -> [b][e][t] fp16 ----------------
__global__ __launch_bounds__(256) void k_vt() {
    __shared__ fp16 tile[32][34];
    int e0 = blockIdx.x * 32, t0 = blockIdx.y * 32, b = blockIdx.z;
    int tx = threadIdx.x, ty = threadIdx.y;   // block (32,8)
    #pragma unroll
    for (int i = 0; i < 4; i++) {
        int t = t0 + ty + i*8;
        tile[ty + i*8][tx] = g_vh[((size_t)b*S_ + t)*E_ + e0 + tx];
    }
    __syncthreads();
    #pragma unroll
    for (int i = 0; i < 4; i++) {
        int e = e0 + ty + i*8;
        size_t o = ((size_t)b*E_ + e)*S_ + t0 + tx;
        g_vth[o] = tile[tx][ty + i*8];
    }
}

// =================================================================
// mma.sync fp16 GEMM: 128x128 CTA tile, 8 warps (4m x 2n, 32x64 each),
// BK=32 double-buffered cp.async.
// MODE 1: D = Ah*Bh                     (single pass)
// MODE 2: D = Ah*Bh + Ah*Bl             (B split)
// MODE 3: D = Ah*Bh + Ah*Bl + Al*Bh     (full split)
// EPI: 0=uv  1=qk  2=pv  3=out
// bn0: column-tile offset (lets uv run two grids with different MODE)
// =================================================================
#define KPAD   40            // fp16 elements per smem row (32 + 8 pad)
#define ARR_B  (128*KPAD*2)  // 10240 bytes per operand array
#define BUF_B  (4*ARR_B)     // 40960 per stage
#define SMEMSZ (2*BUF_B)     // 81920

template<int EPI, int MODE>
__global__ __launch_bounds__(256) void k_gemm(const float* __restrict__ aux,
                                              const float* __restrict__ aux2,
                                              float* __restrict__ fout,
                                              int bn0) {
    constexpr int LD = (EPI==0) ? 512 : (EPI==1) ? 128 : (EPI==2) ? 512 : 1024;
    constexpr int NS = LD / 32;
    constexpr bool BLO   = (MODE >= 2);
    constexpr bool THREE = (MODE >= 3);

    extern __shared__ __align__(16) char smem[];
    const uint32_t sb = smem_u32(smem);
    const int tid = threadIdx.x, wid = tid >> 5, lane = tid & 31;
    const int bm = blockIdx.y * 128, bn = bn0 + blockIdx.x * 128, bz = blockIdx.z;

    const fp16 *Ah, *Al, *Bh, *Bl;
    if (EPI == 0)      { Ah = g_xnh; Al = g_xnl; Bh = g_wh;  Bl = g_wl; }
    else if (EPI == 1) { size_t o = (size_t)bz*S_*SD_;
                         Ah = g_qh+o; Al = g_ql+o; Bh = g_kh+o; Bl = g_kl+o; }
    else if (EPI == 2) { size_t oa = (size_t)bz*S_*S_, ob = (size_t)bz*E_*S_;
                         Ah = g_p+oa; Al = g_p+oa; Bh = g_vth+ob; Bl = g_vth+ob; }
    else               { Ah = g_gt; Al = g_gt; Bh = g_owh; Bl = g_owh; }

    const int lrow = tid >> 1;
    const int lc   = (tid & 1) * 16;
    const fp16* gAh = Ah + (size_t)(bm + lrow) * LD + lc;
    const fp16* gAl = Al + (size_t)(bm + lrow) * LD + lc;
    const fp16* gBh = Bh + (size_t)(bn + lrow) * LD + lc;
    const fp16* gBl = Bl + (size_t)(bn + lrow) * LD + lc;
    const uint32_t srow = sb + lrow * (KPAD*2) + lc * 2;

    auto load_stage = [&](int s) {
        const uint32_t d = srow + (s & 1) * BUF_B;
        const int off = s * 32;
        cpa16(d + 0*ARR_B,      gAh + off); cpa16(d + 0*ARR_B + 16, gAh + off + 8);
        if (THREE) {
            cpa16(d + 1*ARR_B,      gAl + off); cpa16(d + 1*ARR_B + 16, gAl + off + 8);
        }
        cpa16(d + 2*ARR_B,      gBh + off); cpa16(d + 2*ARR_B + 16, gBh + off + 8);
        if (BLO) {
            cpa16(d + 3*ARR_B,      gBl + off); cpa16(d + 3*ARR_B + 16, gBl + off + 8);
        }
    };

    load_stage(0); CP_COMMIT();
    load_stage(1); CP_COMMIT();

    const int am = (wid & 3) * 32;      // warp rows
    const int an = (wid >> 2) * 64;     // warp cols
    float acc[2][8][4];
    #pragma unroll
    for (int mt = 0; mt < 2; mt++)
        #pragma unroll
        for (int nt = 0; nt < 8; nt++)
            #pragma unroll
            for (int j = 0; j < 4; j++) acc[mt][nt][j] = 0.f;

    const int a_row = am + (lane & 15);
    const int a_col = (lane >> 4) * 8;
    const int b_row = an + ((lane >> 4) & 1) * 8 + (lane & 7);
    const int b_col = ((lane >> 3) & 1) * 8;

    for (int s = 0; s < NS; s++) {
        if (s + 1 < NS) { CP_WAIT(1); } else { CP_WAIT(0); }
        __syncthreads();
        const uint32_t bufb = sb + (s & 1) * BUF_B;
        #pragma unroll
        for (int kk = 0; kk < 32; kk += 16) {
            uint32_t ah[2][4], al[2][4];
            #pragma unroll
            for (int mt = 0; mt < 2; mt++) {
                uint32_t ad = bufb + (a_row + mt*16) * (KPAD*2) + (kk + a_col) * 2;
                ldm4(ah[mt], ad);
                if (THREE) ldm4(al[mt], ad + ARR_B);
            }
            uint32_t bh[8][2], bl[8][2];
            #pragma unroll
            for (int n2 = 0; n2 < 4; n2++) {
                uint32_t bd = bufb + 2*ARR_B + (b_row + n2*16) * (KPAD*2) + (kk + b_col) * 2;
                uint32_t r[4];
                ldm4(r, bd);
                bh[n2*2][0]=r[0]; bh[n2*2][1]=r[1]; bh[n2*2+1][0]=r[2]; bh[n2*2+1][1]=r[3];
                if (BLO) {
                    ldm4(r, bd + ARR_B);
                    bl[n2*2][0]=r[0]; bl[n2*2][1]=r[1]; bl[n2*2+1][0]=r[2]; bl[n2*2+1][1]=r[3];
                }
            }
            #pragma unroll
            for (int mt = 0; mt < 2; mt++)
                #pragma unroll
                for (int nt = 0; nt < 8; nt++) {
                    mma16816(acc[mt][nt], ah[mt], bh[nt]);
                    if (BLO)   mma16816(acc[mt][nt], ah[mt], bl[nt]);
                    if (THREE) mma16816(acc[mt][nt], al[mt], bh[nt]);
                }
        }
        __syncthreads();
        if (s + 2 < NS) { load_stage(s + 2); CP_COMMIT(); }
    }

    // -------- epilogue --------
    const int r4 = lane >> 2, c2 = (lane & 3) * 2;
    #pragma unroll
    for (int mt = 0; mt < 2; mt++)
        #pragma unroll
        for (int half = 0; half < 2; half++) {
            const int row = bm + am + mt*16 + half*8 + r4;
            #pragma unroll
            for (int nt = 0; nt < 8; nt++) {
                const int col = bn + an + nt*8 + c2;
                float v0 = acc[mt][nt][half*2 + 0];
                float v1 = acc[mt][nt][half*2 + 1];

                if (EPI == 0) {
                    float a0 = v0 + aux[col], a1 = v1 + aux[col+1];
                    a0 = a0 / (1.0f + expf(-a0));
                    a1 = a1 / (1.0f + expf(-a1));
                    if (col < E_)
                        *(uint32_t*)(g_uh + (size_t)row*E_ + col) =
                            packh(__float2half_rn(a0), __float2half_rn(a1));
                    else if (col < 2*E_)
                        *(uint32_t*)(g_vh + (size_t)row*E_ + (col - E_)) =
                            packh(__float2half_rn(a0), __float2half_rn(a1));
                    else
                        *(float2*)(g_base + (size_t)row*SD_ + (col - 2*E_)) = make_float2(a0, a1);
                } else if (EPI == 1) {
                    float a0 = (v0 + aux[col     - row + (S_-1)]) / 11.313708498984761f;
                    float a1 = (v1 + aux[col + 1 - row + (S_-1)]) / 11.313708498984761f;
                    a0 = fmaxf(a0, 0.f); a1 = fmaxf(a1, 0.f);
                    a0 *= a0; a1 *= a1;
                    size_t o = (size_t)bz*S_*S_ + (size_t)row*S_ + col;
                    *(uint32_t*)(g_p + o) = packh(__float2half_rn(a0), __float2half_rn(a1));
                } else if (EPI == 2) {
                    size_t rr = (size_t)bz*S_ + row;
                    __half2 u2 = *(const __half2*)(g_uh + rr*E_ + col);
                    float a0 = v0 * __half2float(u2.x), a1 = v1 * __half2float(u2.y);
                    *(uint32_t*)(g_gt + rr*E_ + col) = packh(__float2half_rn(a0), __float2half_rn(a1));
                } else {
                    size_t o = (size_t)row*H_ + col;
                    float a0 = v0 + aux[col]     + aux2[o];
                    float a1 = v1 + aux[col + 1] + aux2[o + 1];
                    *(float2*)(fout + o) = make_float2(a0, a1);
                }
            }
        }
}

// ---------------- launch ----------------
extern "C" void kernel_launch(void* const* d_in, const int* in_sizes, int n_in,
                              void* d_out, int out_size) {
    const float* x    = (const float*)d_in[0];
    const float* ln_g = (const float*)d_in[1];
    const float* uv_w = (const float*)d_in[2];
    const float* uv_b = (const float*)d_in[3];
    const float* gam  = (const float*)d_in[4];
    const float* bet  = (const float*)d_in[5];
    const float* wb   = (const float*)d_in[6];
    const float* o_w  = (const float*)d_in[7];
    const float* o_b  = (const float*)d_in[8];
    float* out = (float*)d_out;

    static bool attr_done = false;
    if (!attr_done) {
        cudaFuncSetAttribute(k_gemm<0,1>, cudaFuncAttributeMaxDynamicSharedMemorySize, SMEMSZ);
        cudaFuncSetAttribute(k_gemm<0,3>, cudaFuncAttributeMaxDynamicSharedMemorySize, SMEMSZ);
        cudaFuncSetAttribute(k_gemm<1,3>, cudaFuncAttributeMaxDynamicSharedMemorySize, SMEMSZ);
        cudaFuncSetAttribute(k_gemm<2,1>, cudaFuncAttributeMaxDynamicSharedMemorySize, SMEMSZ);
        cudaFuncSetAttribute(k_gemm<3,1>, cudaFuncAttributeMaxDynamicSharedMemorySize, SMEMSZ);
        attr_done = true;
    }

    fp16 *wh, *wl, *owh;
    cudaGetSymbolAddress((void**)&wh,  g_wh);
    cudaGetSymbolAddress((void**)&wl,  g_wl);
    cudaGetSymbolAddress((void**)&owh, g_owh);

    k_norm  <<<M_, 128>>>(x, ln_g);
    k_split <<<(UV_*H_/4 + 255)/256, 256>>>(uv_w, wh, wl, UV_*H_/4);
    k_split <<<(H_*E_/4 + 255)/256, 256>>>(o_w, owh, nullptr, H_*E_/4);
    k_sincos<<<S_, 64>>>();

    // uv: u/v columns 1-pass, base columns 3-pass
    k_gemm<0,1><<<dim3(16, M_/128), 256, SMEMSZ>>>(uv_b, nullptr, nullptr, 0);
    k_gemm<0,3><<<dim3(1,  M_/128), 256, SMEMSZ>>>(uv_b, nullptr, nullptr, 2048);
    k_rope  <<<M_, 64>>>(gam, bet);
    k_vt    <<<dim3(E_/32, S_/32, B_), dim3(32, 8)>>>();
    k_gemm<1,3><<<dim3(S_/128, S_/128, B_), 256, SMEMSZ>>>(wb, nullptr, nullptr, 0);
    k_gemm<2,1><<<dim3(E_/128, S_/128, B_), 256, SMEMSZ>>>(nullptr, nullptr, nullptr, 0);
    k_gemm<3,1><<<dim3(H_/128, M_/128), 256, SMEMSZ>>>(o_b, x, out, 0);
}

// round 8
// speedup vs baseline: 4.3266x; 1.0583x over previous
#include <cuda_runtime.h>
#include <cuda_fp16.h>
#include <math.h>
#include <stdint.h>

#define B_   64
#define S_   512
#define H_   512
#define E_   1024
#define UV_  2176
#define SD_  128
#define M_   (B_*S_)

typedef __half fp16;

// ---------------- scratch (device globals) ----------------
__device__ __align__(16) fp16  g_xnh[(size_t)M_*H_];
__device__ __align__(16) fp16  g_xnl[(size_t)M_*H_];
__device__ __align__(16) fp16  g_wh [(size_t)UV_*H_];
__device__ __align__(16) fp16  g_wl [(size_t)UV_*H_];
__device__ __align__(16) fp16  g_owh[(size_t)H_*E_];
__device__ __align__(16) fp16  g_uh [(size_t)M_*E_];      // u, fp16
__device__ __align__(16) fp16  g_vh [(size_t)M_*E_];      // v [b][t][e], fp16
__device__ __align__(16) float g_base[(size_t)M_*SD_];
__device__ __align__(16) fp16  g_qh[(size_t)M_*SD_];
__device__ __align__(16) fp16  g_ql[(size_t)M_*SD_];
__device__ __align__(16) fp16  g_kh[(size_t)M_*SD_];
__device__ __align__(16) fp16  g_kl[(size_t)M_*SD_];
__device__ __align__(16) fp16  g_p [(size_t)B_*S_*S_];    // scores, fp16
__device__ __align__(16) fp16  g_gt[(size_t)M_*E_];       // gated, fp16
__device__ float g_sin[S_*64];
__device__ float g_cos[S_*64];

// ---------------- helpers ----------------
__device__ __forceinline__ uint32_t smem_u32(const void* p) {
    uint32_t a;
    asm("{ .reg .u64 t; cvta.to.shared.u64 t, %1; cvt.u32.u64 %0, t; }" : "=r"(a) : "l"(p));
    return a;
}
__device__ __forceinline__ void cpa16(uint32_t s, const void* g) {
    asm volatile("cp.async.cg.shared.global [%0], [%1], 16;" :: "r"(s), "l"(g));
}
#define CP_COMMIT() asm volatile("cp.async.commit_group;")
#define CP_WAIT(n)  asm volatile("cp.async.wait_group %0;" :: "n"(n) : "memory")

__device__ __forceinline__ void ldm4(uint32_t* r, uint32_t a) {
    asm volatile("ldmatrix.sync.aligned.m8n8.x4.shared.b16 {%0,%1,%2,%3},[%4];"
                 : "=r"(r[0]), "=r"(r[1]), "=r"(r[2]), "=r"(r[3]) : "r"(a));
}
__device__ __forceinline__ void ldm4t(uint32_t* r, uint32_t a) {
    asm volatile("ldmatrix.sync.aligned.m8n8.x4.trans.shared.b16 {%0,%1,%2,%3},[%4];"
                 : "=r"(r[0]), "=r"(r[1]), "=r"(r[2]), "=r"(r[3]) : "r"(a));
}
__device__ __forceinline__ void mma16816(float* d, const uint32_t* a, const uint32_t* b) {
    asm volatile("mma.sync.aligned.m16n8k16.row.col.f32.f16.f16.f32 "
                 "{%0,%1,%2,%3},{%4,%5,%6,%7},{%8,%9},{%0,%1,%2,%3};"
                 : "+f"(d[0]), "+f"(d[1]), "+f"(d[2]), "+f"(d[3])
                 : "r"(a[0]), "r"(a[1]), "r"(a[2]), "r"(a[3]), "r"(b[0]), "r"(b[1]));
}
__device__ __forceinline__ void split2(float x, fp16& h, fp16& l) {
    h = __float2half_rn(x);
    l = __float2half_rn(x - __half2float(h));
}
__device__ __forceinline__ uint32_t packh(fp16 a, fp16 b) {
    return (uint32_t)__half_as_ushort(a) | ((uint32_t)__half_as_ushort(b) << 16);
}

// ---------------- norm -> split fp16 ----------------
__global__ __launch_bounds__(128) void k_norm(const float* __restrict__ x,
                                              const float* __restrict__ ln_g) {
    int row = blockIdx.x;
    const float4* xr = (const float4*)(x + (size_t)row * H_);
    float4 a = xr[threadIdx.x];
    float ss = a.x*a.x + a.y*a.y + a.z*a.z + a.w*a.w;
    #pragma unroll
    for (int o = 16; o; o >>= 1) ss += __shfl_xor_sync(0xffffffffu, ss, o);
    __shared__ float ws[4];
    if ((threadIdx.x & 31) == 0) ws[threadIdx.x >> 5] = ss;
    __syncthreads();
    float total = ws[0] + ws[1] + ws[2] + ws[3];
    float norm = sqrtf(total * (1.0f / (float)H_));
    float sc = ln_g[0] / fmaxf(norm, 1e-5f);
    float v[4] = {a.x*sc, a.y*sc, a.z*sc, a.w*sc};
    fp16 h[4], l[4];
    #pragma unroll
    for (int i = 0; i < 4; i++) split2(v[i], h[i], l[i]);
    size_t off = (size_t)row * H_ + threadIdx.x * 4;
    *(uint2*)(g_xnh + off) = *(uint2*)h;
    *(uint2*)(g_xnl + off) = *(uint2*)l;
}

// ---------------- generic fp32 -> fp16 hi/lo split ----------------
__global__ __launch_bounds__(256) void k_split(const float* __restrict__ src,
                                               fp16* __restrict__ dh, fp16* __restrict__ dl,
                                               int n4) {
    int i = blockIdx.x * blockDim.x + threadIdx.x;
    if (i >= n4) return;
    float4 a = ((const float4*)src)[i];
    float v[4] = {a.x, a.y, a.z, a.w};
    fp16 h[4], l[4];
    #pragma unroll
    for (int k = 0; k < 4; k++) split2(v[k], h[k], l[k]);
    *(uint2*)(dh + (size_t)i*4) = *(uint2*)h;
    if (dl) *(uint2*)(dl + (size_t)i*4) = *(uint2*)l;
}

// ---------------- sin/cos table: double-precision provenance ----------------
__global__ void k_sincos() {
    int s = blockIdx.x, d = threadIdx.x;
    double invf_d = pow(10000.0, (double)d / 64.0);
    float invf = (float)invf_d;
    float arg = (float)s * invf;
    double a = (double)arg;
    g_sin[s*64 + d] = (float)sin(a);
    g_cos[s*64 + d] = (float)cos(a);
}

// ---------------- gamma/beta + RoPE -> split q,k ----------------
__global__ __launch_bounds__(64) void k_rope(const float* __restrict__ gamma,
                                             const float* __restrict__ beta) {
    int row = blockIdx.x;
    int s = row & (S_ - 1);
    int d = threadIdx.x;
    const float* base = g_base + (size_t)row * SD_;
    float b1 = base[d], b2 = base[d + 64];
    float sn = g_sin[s*64 + d], cs = g_cos[s*64 + d];
    float x1 = b1 * gamma[d]      + beta[d];
    float x2 = b2 * gamma[d + 64] + beta[d + 64];
    float q0 = x1*cs - x2*sn, q1 = x2*cs + x1*sn;
    float y1 = b1 * gamma[128 + d]      + beta[128 + d];
    float y2 = b2 * gamma[128 + 64 + d] + beta[128 + 64 + d];
    float k0 = y1*cs - y2*sn, k1 = y2*cs + y1*sn;
    size_t o = (size_t)row * SD_;
    fp16 h, l;
    split2(q0, h, l); g_qh[o+d] = h;    g_ql[o+d] = l;
    split2(q1, h, l); g_qh[o+d+64] = h; g_ql[o+d+64] = l;
    split2(k0, h, l); g_kh[o+d] = h;    g_kl[o+d] = l;
    split2(k1, h, l); g_kh[o+d+64] = h; g_kl[o+d+64] = l;
}

// =================================================================
// mma.sync fp16 GEMM: 128x128 CTA tile, 8 warps (4m x 2n, 32x64 each),
// BK=32 double-buffered cp.async.
// MODE 1: D = Ah*Bh ; MODE 2: += Ah*Bl ; MODE 3: += Al*Bh
// EPI: 0=uv  1=qk  2=pv(B loaded [k][n] + ldmatrix.trans)  3=out
// =================================================================
#define KPAD    40             // fp16 per smem row (32 + 8 pad) for K-major arrays
#define ARR_B   (128*KPAD*2)   // 10240 B per K-major operand array
#define BUF_B   (4*ARR_B)      // 40960 per stage (generic layout)
#define SMEMSZ  (2*BUF_B)      // 81920
// pv-specific: B tile [32 k][128 n] fp16, 272B per row (256 + 16 pad)
#define BT_ROW  272
#define BT_ARR  (32*BT_ROW)            // 8704
#define BUF2_B  (ARR_B + BT_ARR)       // 18944 per stage
#define SMEMSZ2 (2*BUF2_B)             // 37888

template<int EPI, int MODE>
__global__ __launch_bounds__(256) void k_gemm(const float* __restrict__ aux,
                                              const float* __restrict__ aux2,
                                              float* __restrict__ fout,
                                              int bn0) {
    constexpr int LD = (EPI==0) ? 512 : (EPI==1) ? 128 : (EPI==2) ? 512 : 1024;
    constexpr int NS = LD / 32;
    constexpr bool BLO   = (MODE >= 2);
    constexpr bool THREE = (MODE >= 3);
    constexpr bool BT    = (EPI == 2);     // B from [k][n] layout via ldmatrix.trans

    extern __shared__ __align__(16) char smem[];
    const uint32_t sb = smem_u32(smem);
    const int tid = threadIdx.x, wid = tid >> 5, lane = tid & 31;
    const int bm = blockIdx.y * 128, bn = bn0 + blockIdx.x * 128, bz = blockIdx.z;

    const fp16 *Ah, *Al, *Bh, *Bl;
    if (EPI == 0)      { Ah = g_xnh; Al = g_xnl; Bh = g_wh;  Bl = g_wl; }
    else if (EPI == 1) { size_t o = (size_t)bz*S_*SD_;
                         Ah = g_qh+o; Al = g_ql+o; Bh = g_kh+o; Bl = g_kl+o; }
    else if (EPI == 2) { Ah = g_p + (size_t)bz*S_*S_; Al = Ah;
                         Bh = g_vh + (size_t)bz*S_*E_; Bl = Bh; }
    else               { Ah = g_gt; Al = g_gt; Bh = g_owh; Bl = g_owh; }

    const int lrow = tid >> 1;
    const int lc   = (tid & 1) * 16;
    const fp16* gAh = Ah + (size_t)(bm + lrow) * LD + lc;
    const fp16* gAl = Al + (size_t)(bm + lrow) * LD + lc;
    const fp16* gBh = Bh + (size_t)(bn + lrow) * LD + lc;
    const fp16* gBl = Bl + (size_t)(bn + lrow) * LD + lc;
    const uint32_t srowA = sb + lrow * (KPAD*2) + lc * 2;
    // pv B load mapping: 32 rows x 256B; 8 threads/row, 32B each
    const int btrow = tid >> 3;
    const int btcol = (tid & 7) * 32;                    // bytes within row
    const fp16* gBt = (EPI == 2) ? Bh + btcol/2 + bn : nullptr;

    auto load_stage = [&](int s) {
        if (BT) {
            const uint32_t st = sb + (s & 1) * BUF2_B;
            const int off = s * 32;
            cpa16(st + srowA - sb, gAh + off);
            cpa16(st + srowA - sb + 16, gAh + off + 8);
            const uint32_t bd = st + ARR_B + btrow * BT_ROW + btcol;
            const fp16* gsrc = gBt + (size_t)(off + btrow) * E_;
            cpa16(bd, gsrc); cpa16(bd + 16, gsrc + 8);
        } else {
            const uint32_t d = srowA + (s & 1) * BUF_B;
            const int off = s * 32;
            cpa16(d + 0*ARR_B,      gAh + off); cpa16(d + 0*ARR_B + 16, gAh + off + 8);
            if (THREE) {
                cpa16(d + 1*ARR_B,      gAl + off); cpa16(d + 1*ARR_B + 16, gAl + off + 8);
            }
            cpa16(d + 2*ARR_B,      gBh + off); cpa16(d + 2*ARR_B + 16, gBh + off + 8);
            if (BLO) {
                cpa16(d + 3*ARR_B,      gBl + off); cpa16(d + 3*ARR_B + 16, gBl + off + 8);
            }
        }
    };

    load_stage(0); CP_COMMIT();
    load_stage(1); CP_COMMIT();

    const int am = (wid & 3) * 32;      // warp rows
    const int an = (wid >> 2) * 64;     // warp cols
    float acc[2][8][4];
    #pragma unroll
    for (int mt = 0; mt < 2; mt++)
        #pragma unroll
        for (int nt = 0; nt < 8; nt++)
            #pragma unroll
            for (int j = 0; j < 4; j++) acc[mt][nt][j] = 0.f;

    const int a_row = am + (lane & 15);
    const int a_col = (lane >> 4) * 8;
    const int b_row = an + ((lane >> 4) & 1) * 8 + (lane & 7);
    const int b_col = ((lane >> 3) & 1) * 8;
    // trans-B addressing: row = k, col = n
    const int bt_k = lane & 15;
    const int bt_n = (lane >> 4) * 8;

    for (int s = 0; s < NS; s++) {
        if (s + 1 < NS) { CP_WAIT(1); } else { CP_WAIT(0); }
        __syncthreads();
        const uint32_t bufb = sb + (s & 1) * (BT ? BUF2_B : BUF_B);
        #pragma unroll
        for (int kk = 0; kk < 32; kk += 16) {
            uint32_t ah[2][4], al[2][4];
            #pragma unroll
            for (int mt = 0; mt < 2; mt++) {
                uint32_t ad = bufb + (a_row + mt*16) * (KPAD*2) + (kk + a_col) * 2;
                ldm4(ah[mt], ad);
                if (THREE) ldm4(al[mt], ad + ARR_B);
            }
            uint32_t bh[8][2], bl[8][2];
            #pragma unroll
            for (int n2 = 0; n2 < 4; n2++) {
                uint32_t r[4];
                if (BT) {
                    uint32_t bd = bufb + ARR_B + (kk + bt_k) * BT_ROW
                                  + (an + n2*16 + bt_n) * 2;
                    ldm4t(r, bd);
                    bh[n2*2][0]=r[0]; bh[n2*2][1]=r[1]; bh[n2*2+1][0]=r[2]; bh[n2*2+1][1]=r[3];
                } else {
                    uint32_t bd = bufb + 2*ARR_B + (b_row + n2*16) * (KPAD*2) + (kk + b_col) * 2;
                    ldm4(r, bd);
                    bh[n2*2][0]=r[0]; bh[n2*2][1]=r[1]; bh[n2*2+1][0]=r[2]; bh[n2*2+1][1]=r[3];
                    if (BLO) {
                        ldm4(r, bd + ARR_B);
                        bl[n2*2][0]=r[0]; bl[n2*2][1]=r[1]; bl[n2*2+1][0]=r[2]; bl[n2*2+1][1]=r[3];
                    }
                }
            }
            #pragma unroll
            for (int mt = 0; mt < 2; mt++)
                #pragma unroll
                for (int nt = 0; nt < 8; nt++) {
                    mma16816(acc[mt][nt], ah[mt], bh[nt]);
                    if (BLO)   mma16816(acc[mt][nt], ah[mt], bl[nt]);
                    if (THREE) mma16816(acc[mt][nt], al[mt], bh[nt]);
                }
        }
        __syncthreads();
        if (s + 2 < NS) { load_stage(s + 2); CP_COMMIT(); }
    }

    // -------- epilogue --------
    const int r4 = lane >> 2, c2 = (lane & 3) * 2;
    #pragma unroll
    for (int mt = 0; mt < 2; mt++)
        #pragma unroll
        for (int half = 0; half < 2; half++) {
            const int row = bm + am + mt*16 + half*8 + r4;
            #pragma unroll
            for (int nt = 0; nt < 8; nt++) {
                const int col = bn + an + nt*8 + c2;
                float v0 = acc[mt][nt][half*2 + 0];
                float v1 = acc[mt][nt][half*2 + 1];

                if (EPI == 0) {
                    float a0 = v0 + aux[col], a1 = v1 + aux[col+1];
                    a0 = a0 / (1.0f + expf(-a0));
                    a1 = a1 / (1.0f + expf(-a1));
                    if (col < E_)
                        *(uint32_t*)(g_uh + (size_t)row*E_ + col) =
                            packh(__float2half_rn(a0), __float2half_rn(a1));
                    else if (col < 2*E_)
                        *(uint32_t*)(g_vh + (size_t)row*E_ + (col - E_)) =
                            packh(__float2half_rn(a0), __float2half_rn(a1));
                    else
                        *(float2*)(g_base + (size_t)row*SD_ + (col - 2*E_)) = make_float2(a0, a1);
                } else if (EPI == 1) {
                    float a0 = (v0 + aux[col     - row + (S_-1)]) / 11.313708498984761f;
                    float a1 = (v1 + aux[col + 1 - row + (S_-1)]) / 11.313708498984761f;
                    a0 = fmaxf(a0, 0.f); a1 = fmaxf(a1, 0.f);
                    a0 *= a0; a1 *= a1;
                    size_t o = (size_t)bz*S_*S_ + (size_t)row*S_ + col;
                    *(uint32_t*)(g_p + o) = packh(__float2half_rn(a0), __float2half_rn(a1));
                } else if (EPI == 2) {
                    size_t rr = (size_t)bz*S_ + row;
                    __half2 u2 = *(const __half2*)(g_uh + rr*E_ + col);
                    float a0 = v0 * __half2float(u2.x), a1 = v1 * __half2float(u2.y);
                    *(uint32_t*)(g_gt + rr*E_ + col) = packh(__float2half_rn(a0), __float2half_rn(a1));
                } else {
                    size_t o = (size_t)row*H_ + col;
                    float a0 = v0 + aux[col]     + aux2[o];
                    float a1 = v1 + aux[col + 1] + aux2[o + 1];
                    *(float2*)(fout + o) = make_float2(a0, a1);
                }
            }
        }
}

// ---------------- launch ----------------
extern "C" void kernel_launch(void* const* d_in, const int* in_sizes, int n_in,
                              void* d_out, int out_size) {
    const float* x    = (const float*)d_in[0];
    const float* ln_g = (const float*)d_in[1];
    const float* uv_w = (const float*)d_in[2];
    const float* uv_b = (const float*)d_in[3];
    const float* gam  = (const float*)d_in[4];
    const float* bet  = (const float*)d_in[5];
    const float* wb   = (const float*)d_in[6];
    const float* o_w  = (const float*)d_in[7];
    const float* o_b  = (const float*)d_in[8];
    float* out = (float*)d_out;

    static bool attr_done = false;
    if (!attr_done) {
        cudaFuncSetAttribute(k_gemm<0,1>, cudaFuncAttributeMaxDynamicSharedMemorySize, SMEMSZ);
        cudaFuncSetAttribute(k_gemm<0,3>, cudaFuncAttributeMaxDynamicSharedMemorySize, SMEMSZ);
        cudaFuncSetAttribute(k_gemm<1,3>, cudaFuncAttributeMaxDynamicSharedMemorySize, SMEMSZ);
        cudaFuncSetAttribute(k_gemm<2,1>, cudaFuncAttributeMaxDynamicSharedMemorySize, SMEMSZ2);
        cudaFuncSetAttribute(k_gemm<3,1>, cudaFuncAttributeMaxDynamicSharedMemorySize, SMEMSZ);
        attr_done = true;
    }

    fp16 *wh, *wl, *owh;
    cudaGetSymbolAddress((void**)&wh,  g_wh);
    cudaGetSymbolAddress((void**)&wl,  g_wl);
    cudaGetSymbolAddress((void**)&owh, g_owh);

    k_norm  <<<M_, 128>>>(x, ln_g);
    k_split <<<(UV_*H_/4 + 255)/256, 256>>>(uv_w, wh, wl, UV_*H_/4);
    k_split <<<(H_*E_/4 + 255)/256, 256>>>(o_w, owh, nullptr, H_*E_/4);
    k_sincos<<<S_, 64>>>();

    // uv: u/v columns 1-pass, base columns 3-pass
    k_gemm<0,1><<<dim3(16, M_/128), 256, SMEMSZ>>>(uv_b, nullptr, nullptr, 0);
    k_gemm<0,3><<<dim3(1,  M_/128), 256, SMEMSZ>>>(uv_b, nullptr, nullptr, 2048);
    k_rope  <<<M_, 64>>>(gam, bet);
    k_gemm<1,3><<<dim3(S_/128, S_/128, B_), 256, SMEMSZ>>>(wb, nullptr, nullptr, 0);
    k_gemm<2,1><<<dim3(E_/128, S_/128, B_), 256, SMEMSZ2>>>(nullptr, nullptr, nullptr, 0);
    k_gemm<3,1><<<dim3(H_/128, M_/128), 256, SMEMSZ>>>(o_b, x, out, 0);
}

// round 9
// speedup vs baseline: 4.4393x; 1.0260x over previous
#include <cuda_runtime.h>
#include <cuda_fp16.h>
#include <math.h>
#include <stdint.h>

#define B_   64
#define S_   512
#define H_   512
#define E_   1024
#define UV_  2176
#define SD_  128
#define M_   (B_*S_)

typedef __half fp16;

// ---------------- scratch (device globals) ----------------
__device__ __align__(16) fp16  g_xnh[(size_t)M_*H_];
__device__ __align__(16) fp16  g_xnl[(size_t)M_*H_];
__device__ __align__(16) fp16  g_wh [(size_t)UV_*H_];
__device__ __align__(16) fp16  g_wl [(size_t)UV_*H_];
__device__ __align__(16) fp16  g_owh[(size_t)H_*E_];
__device__ __align__(16) fp16  g_uh [(size_t)M_*E_];      // u, fp16
__device__ __align__(16) fp16  g_vh [(size_t)M_*E_];      // v [b][t][e], fp16
__device__ __align__(16) float g_base[(size_t)M_*SD_];
__device__ __align__(16) fp16  g_qh[(size_t)M_*SD_];
__device__ __align__(16) fp16  g_ql[(size_t)M_*SD_];
__device__ __align__(16) fp16  g_kh[(size_t)M_*SD_];
__device__ __align__(16) fp16  g_kl[(size_t)M_*SD_];
__device__ __align__(16) fp16  g_p [(size_t)B_*S_*S_];    // scores, fp16
__device__ __align__(16) fp16  g_gt[(size_t)M_*E_];       // gated, fp16
__device__ float g_sin[S_*64];
__device__ float g_cos[S_*64];

// ---------------- helpers ----------------
__device__ __forceinline__ uint32_t smem_u32(const void* p) {
    uint32_t a;
    asm("{ .reg .u64 t; cvta.to.shared.u64 t, %1; cvt.u32.u64 %0, t; }" : "=r"(a) : "l"(p));
    return a;
}
__device__ __forceinline__ void cpa16(uint32_t s, const void* g) {
    asm volatile("cp.async.cg.shared.global [%0], [%1], 16;" :: "r"(s), "l"(g));
}
#define CP_COMMIT() asm volatile("cp.async.commit_group;")
#define CP_WAIT(n)  asm volatile("cp.async.wait_group %0;" :: "n"(n) : "memory")

__device__ __forceinline__ void ldm4(uint32_t* r, uint32_t a) {
    asm volatile("ldmatrix.sync.aligned.m8n8.x4.shared.b16 {%0,%1,%2,%3},[%4];"
                 : "=r"(r[0]), "=r"(r[1]), "=r"(r[2]), "=r"(r[3]) : "r"(a));
}
__device__ __forceinline__ void ldm4t(uint32_t* r, uint32_t a) {
    asm volatile("ldmatrix.sync.aligned.m8n8.x4.trans.shared.b16 {%0,%1,%2,%3},[%4];"
                 : "=r"(r[0]), "=r"(r[1]), "=r"(r[2]), "=r"(r[3]) : "r"(a));
}
__device__ __forceinline__ void mma16816(float* d, const uint32_t* a, const uint32_t* b) {
    asm volatile("mma.sync.aligned.m16n8k16.row.col.f32.f16.f16.f32 "
                 "{%0,%1,%2,%3},{%4,%5,%6,%7},{%8,%9},{%0,%1,%2,%3};"
                 : "+f"(d[0]), "+f"(d[1]), "+f"(d[2]), "+f"(d[3])
                 : "r"(a[0]), "r"(a[1]), "r"(a[2]), "r"(a[3]), "r"(b[0]), "r"(b[1]));
}
__device__ __forceinline__ void split2(float x, fp16& h, fp16& l) {
    h = __float2half_rn(x);
    l = __float2half_rn(x - __half2float(h));
}
__device__ __forceinline__ uint32_t packh(fp16 a, fp16 b) {
    return (uint32_t)__half_as_ushort(a) | ((uint32_t)__half_as_ushort(b) << 16);
}

// ---------------- norm -> split fp16 ----------------
__global__ __launch_bounds__(128) void k_norm(const float* __restrict__ x,
                                              const float* __restrict__ ln_g) {
    int row = blockIdx.x;
    const float4* xr = (const float4*)(x + (size_t)row * H_);
    float4 a = xr[threadIdx.x];
    float ss = a.x*a.x + a.y*a.y + a.z*a.z + a.w*a.w;
    #pragma unroll
    for (int o = 16; o; o >>= 1) ss += __shfl_xor_sync(0xffffffffu, ss, o);
    __shared__ float ws[4];
    if ((threadIdx.x & 31) == 0) ws[threadIdx.x >> 5] = ss;
    __syncthreads();
    float total = ws[0] + ws[1] + ws[2] + ws[3];
    float norm = sqrtf(total * (1.0f / (float)H_));
    float sc = ln_g[0] / fmaxf(norm, 1e-5f);
    float v[4] = {a.x*sc, a.y*sc, a.z*sc, a.w*sc};
    fp16 h[4], l[4];
    #pragma unroll
    for (int i = 0; i < 4; i++) split2(v[i], h[i], l[i]);
    size_t off = (size_t)row * H_ + threadIdx.x * 4;
    *(uint2*)(g_xnh + off) = *(uint2*)h;
    *(uint2*)(g_xnl + off) = *(uint2*)l;
}

// ---------------- generic fp32 -> fp16 hi/lo split ----------------
__global__ __launch_bounds__(256) void k_split(const float* __restrict__ src,
                                               fp16* __restrict__ dh, fp16* __restrict__ dl,
                                               int n4) {
    int i = blockIdx.x * blockDim.x + threadIdx.x;
    if (i >= n4) return;
    float4 a = ((const float4*)src)[i];
    float v[4] = {a.x, a.y, a.z, a.w};
    fp16 h[4], l[4];
    #pragma unroll
    for (int k = 0; k < 4; k++) split2(v[k], h[k], l[k]);
    *(uint2*)(dh + (size_t)i*4) = *(uint2*)h;
    if (dl) *(uint2*)(dl + (size_t)i*4) = *(uint2*)l;
}

// ---------------- sin/cos table: double-precision provenance ----------------
__global__ void k_sincos() {
    int s = blockIdx.x, d = threadIdx.x;
    double invf_d = pow(10000.0, (double)d / 64.0);
    float invf = (float)invf_d;
    float arg = (float)s * invf;
    double a = (double)arg;
    g_sin[s*64 + d] = (float)sin(a);
    g_cos[s*64 + d] = (float)cos(a);
}

// ---------------- gamma/beta + RoPE -> split q,k ----------------
__global__ __launch_bounds__(64) void k_rope(const float* __restrict__ gamma,
                                             const float* __restrict__ beta) {
    int row = blockIdx.x;
    int s = row & (S_ - 1);
    int d = threadIdx.x;
    const float* base = g_base + (size_t)row * SD_;
    float b1 = base[d], b2 = base[d + 64];
    float sn = g_sin[s*64 + d], cs = g_cos[s*64 + d];
    float x1 = b1 * gamma[d]      + beta[d];
    float x2 = b2 * gamma[d + 64] + beta[d + 64];
    float q0 = x1*cs - x2*sn, q1 = x2*cs + x1*sn;
    float y1 = b1 * gamma[128 + d]      + beta[128 + d];
    float y2 = b2 * gamma[128 + 64 + d] + beta[128 + 64 + d];
    float k0 = y1*cs - y2*sn, k1 = y2*cs + y1*sn;
    size_t o = (size_t)row * SD_;
    fp16 h, l;
    split2(q0, h, l); g_qh[o+d] = h;    g_ql[o+d] = l;
    split2(q1, h, l); g_qh[o+d+64] = h; g_ql[o+d+64] = l;
    split2(k0, h, l); g_kh[o+d] = h;    g_kl[o+d] = l;
    split2(k1, h, l); g_kh[o+d+64] = h; g_kl[o+d+64] = l;
}

// =================================================================
// mma.sync fp16 GEMM: 128x128 CTA tile, 8 warps (4m x 2n, 32x64 each),
// BK=32 double-buffered cp.async.
// MODE 1: D = Ah*Bh ; MODE 2: += Ah*Bl ; MODE 3: += Al*Bh
// EPI: 0=uv  1=qk  2=pv(B loaded [k][n] + ldmatrix.trans)  3=out
// =================================================================
#define KPAD    40             // fp16 per smem row (32 + 8 pad) for K-major arrays
#define ARR_B   (128*KPAD*2)   // 10240 B per K-major operand array
#define BUF_B   (4*ARR_B)      // 40960 per stage (generic layout)
#define SMEMSZ  (2*BUF_B)      // 81920
// pv-specific: B tile [32 k][128 n] fp16, 272B per row (256 + 16 pad)
#define BT_ROW  272
#define BT_ARR  (32*BT_ROW)            // 8704
#define BUF2_B  (ARR_B + BT_ARR)       // 18944 per stage
#define SMEMSZ2 (2*BUF2_B)             // 37888

template<int EPI, int MODE>
__global__ __launch_bounds__(256) void k_gemm(const float* __restrict__ aux,
                                              const float* __restrict__ aux2,
                                              float* __restrict__ fout,
                                              int bn0) {
    constexpr int LD = (EPI==0) ? 512 : (EPI==1) ? 128 : (EPI==2) ? 512 : 1024;
    constexpr int NS = LD / 32;
    constexpr bool BLO   = (MODE >= 2);
    constexpr bool THREE = (MODE >= 3);
    constexpr bool BT    = (EPI == 2);     // B from [k][n] layout via ldmatrix.trans

    extern __shared__ __align__(16) char smem[];
    const uint32_t sb = smem_u32(smem);
    const int tid = threadIdx.x, wid = tid >> 5, lane = tid & 31;
    const int bm = blockIdx.y * 128, bn = bn0 + blockIdx.x * 128, bz = blockIdx.z;

    const fp16 *Ah, *Al, *Bh, *Bl;
    if (EPI == 0)      { Ah = g_xnh; Al = g_xnl; Bh = g_wh;  Bl = g_wl; }
    else if (EPI == 1) { size_t o = (size_t)bz*S_*SD_;
                         Ah = g_qh+o; Al = g_ql+o; Bh = g_kh+o; Bl = g_kl+o; }
    else if (EPI == 2) { Ah = g_p + (size_t)bz*S_*S_; Al = Ah;
                         Bh = g_vh + (size_t)bz*S_*E_; Bl = Bh; }
    else               { Ah = g_gt; Al = g_gt; Bh = g_owh; Bl = g_owh; }

    const int lrow = tid >> 1;
    const int lc   = (tid & 1) * 16;
    const fp16* gAh = Ah + (size_t)(bm + lrow) * LD + lc;
    const fp16* gAl = Al + (size_t)(bm + lrow) * LD + lc;
    const fp16* gBh = Bh + (size_t)(bn + lrow) * LD + lc;
    const fp16* gBl = Bl + (size_t)(bn + lrow) * LD + lc;
    const uint32_t srowA = sb + lrow * (KPAD*2) + lc * 2;
    // pv B load mapping: 32 rows x 256B; 8 threads/row, 32B each
    const int btrow = tid >> 3;
    const int btcol = (tid & 7) * 32;                    // bytes within row
    const fp16* gBt = (EPI == 2) ? Bh + btcol/2 + bn : nullptr;

    auto load_stage = [&](int s) {
        if (BT) {
            const uint32_t st = sb + (s & 1) * BUF2_B;
            const int off = s * 32;
            cpa16(st + srowA - sb, gAh + off);
            cpa16(st + srowA - sb + 16, gAh + off + 8);
            const uint32_t bd = st + ARR_B + btrow * BT_ROW + btcol;
            const fp16* gsrc = gBt + (size_t)(off + btrow) * E_;
            cpa16(bd, gsrc); cpa16(bd + 16, gsrc + 8);
        } else {
            const uint32_t d = srowA + (s & 1) * BUF_B;
            const int off = s * 32;
            cpa16(d + 0*ARR_B,      gAh + off); cpa16(d + 0*ARR_B + 16, gAh + off + 8);
            if (THREE) {
                cpa16(d + 1*ARR_B,      gAl + off); cpa16(d + 1*ARR_B + 16, gAl + off + 8);
            }
            cpa16(d + 2*ARR_B,      gBh + off); cpa16(d + 2*ARR_B + 16, gBh + off + 8);
            if (BLO) {
                cpa16(d + 3*ARR_B,      gBl + off); cpa16(d + 3*ARR_B + 16, gBl + off + 8);
            }
        }
    };

    load_stage(0); CP_COMMIT();
    load_stage(1); CP_COMMIT();

    const int am = (wid & 3) * 32;      // warp rows
    const int an = (wid >> 2) * 64;     // warp cols
    float acc[2][8][4];
    #pragma unroll
    for (int mt = 0; mt < 2; mt++)
        #pragma unroll
        for (int nt = 0; nt < 8; nt++)
            #pragma unroll
            for (int j = 0; j < 4; j++) acc[mt][nt][j] = 0.f;

    const int a_row = am + (lane & 15);
    const int a_col = (lane >> 4) * 8;
    const int b_row = an + ((lane >> 4) & 1) * 8 + (lane & 7);
    const int b_col = ((lane >> 3) & 1) * 8;
    // trans-B addressing: row = k, col = n
    const int bt_k = lane & 15;
    const int bt_n = (lane >> 4) * 8;

    for (int s = 0; s < NS; s++) {
        if (s + 1 < NS) { CP_WAIT(1); } else { CP_WAIT(0); }
        __syncthreads();
        const uint32_t bufb = sb + (s & 1) * (BT ? BUF2_B : BUF_B);
        #pragma unroll
        for (int kk = 0; kk < 32; kk += 16) {
            uint32_t ah[2][4], al[2][4];
            #pragma unroll
            for (int mt = 0; mt < 2; mt++) {
                uint32_t ad = bufb + (a_row + mt*16) * (KPAD*2) + (kk + a_col) * 2;
                ldm4(ah[mt], ad);
                if (THREE) ldm4(al[mt], ad + ARR_B);
            }
            uint32_t bh[8][2], bl[8][2];
            #pragma unroll
            for (int n2 = 0; n2 < 4; n2++) {
                uint32_t r[4];
                if (BT) {
                    uint32_t bd = bufb + ARR_B + (kk + bt_k) * BT_ROW
                                  + (an + n2*16 + bt_n) * 2;
                    ldm4t(r, bd);
                    bh[n2*2][0]=r[0]; bh[n2*2][1]=r[1]; bh[n2*2+1][0]=r[2]; bh[n2*2+1][1]=r[3];
                } else {
                    uint32_t bd = bufb + 2*ARR_B + (b_row + n2*16) * (KPAD*2) + (kk + b_col) * 2;
                    ldm4(r, bd);
                    bh[n2*2][0]=r[0]; bh[n2*2][1]=r[1]; bh[n2*2+1][0]=r[2]; bh[n2*2+1][1]=r[3];
                    if (BLO) {
                        ldm4(r, bd + ARR_B);
                        bl[n2*2][0]=r[0]; bl[n2*2][1]=r[1]; bl[n2*2+1][0]=r[2]; bl[n2*2+1][1]=r[3];
                    }
                }
            }
            #pragma unroll
            for (int mt = 0; mt < 2; mt++)
                #pragma unroll
                for (int nt = 0; nt < 8; nt++) {
                    mma16816(acc[mt][nt], ah[mt], bh[nt]);
                    if (BLO)   mma16816(acc[mt][nt], ah[mt], bl[nt]);
                    if (THREE) mma16816(acc[mt][nt], al[mt], bh[nt]);
                }
        }
        __syncthreads();
        if (s + 2 < NS) { load_stage(s + 2); CP_COMMIT(); }
    }

    // -------- epilogue --------
    const int r4 = lane >> 2, c2 = (lane & 3) * 2;
    #pragma unroll
    for (int mt = 0; mt < 2; mt++)
        #pragma unroll
        for (int half = 0; half < 2; half++) {
            const int row = bm + am + mt*16 + half*8 + r4;
            #pragma unroll
            for (int nt = 0; nt < 8; nt++) {
                const int col = bn + an + nt*8 + c2;
                float v0 = acc[mt][nt][half*2 + 0];
                float v1 = acc[mt][nt][half*2 + 1];

                if (EPI == 0) {
                    float a0 = v0 + aux[col], a1 = v1 + aux[col+1];
                    a0 = a0 / (1.0f + expf(-a0));
                    a1 = a1 / (1.0f + expf(-a1));
                    if (col < E_)
                        *(uint32_t*)(g_uh + (size_t)row*E_ + col) =
                            packh(__float2half_rn(a0), __float2half_rn(a1));
                    else if (col < 2*E_)
                        *(uint32_t*)(g_vh + (size_t)row*E_ + (col - E_)) =
                            packh(__float2half_rn(a0), __float2half_rn(a1));
                    else
                        *(float2*)(g_base + (size_t)row*SD_ + (col - 2*E_)) = make_float2(a0, a1);
                } else if (EPI == 1) {
                    float a0 = (v0 + aux[col     - row + (S_-1)]) / 11.313708498984761f;
                    float a1 = (v1 + aux[col + 1 - row + (S_-1)]) / 11.313708498984761f;
                    a0 = fmaxf(a0, 0.f); a1 = fmaxf(a1, 0.f);
                    a0 *= a0; a1 *= a1;
                    size_t o = (size_t)bz*S_*S_ + (size_t)row*S_ + col;
                    *(uint32_t*)(g_p + o) = packh(__float2half_rn(a0), __float2half_rn(a1));
                } else if (EPI == 2) {
                    size_t rr = (size_t)bz*S_ + row;
                    __half2 u2 = *(const __half2*)(g_uh + rr*E_ + col);
                    float a0 = v0 * __half2float(u2.x), a1 = v1 * __half2float(u2.y);
                    *(uint32_t*)(g_gt + rr*E_ + col) = packh(__float2half_rn(a0), __float2half_rn(a1));
                } else {
                    size_t o = (size_t)row*H_ + col;
                    float a0 = v0 + aux[col]     + aux2[o];
                    float a1 = v1 + aux[col + 1] + aux2[o + 1];
                    *(float2*)(fout + o) = make_float2(a0, a1);
                }
            }
        }
}

// ---------------- launch ----------------
extern "C" void kernel_launch(void* const* d_in, const int* in_sizes, int n_in,
                              void* d_out, int out_size) {
    const float* x    = (const float*)d_in[0];
    const float* ln_g = (const float*)d_in[1];
    const float* uv_w = (const float*)d_in[2];
    const float* uv_b = (const float*)d_in[3];
    const float* gam  = (const float*)d_in[4];
    const float* bet  = (const float*)d_in[5];
    const float* wb   = (const float*)d_in[6];
    const float* o_w  = (const float*)d_in[7];
    const float* o_b  = (const float*)d_in[8];
    float* out = (float*)d_out;

    static cudaStream_t s1 = nullptr;
    static cudaEvent_t e_fork, e_sin, e_aux, e_base, e_qk;
    static bool init_done = false;
    if (!init_done) {
        cudaFuncSetAttribute(k_gemm<0,1>, cudaFuncAttributeMaxDynamicSharedMemorySize, SMEMSZ);
        cudaFuncSetAttribute(k_gemm<0,3>, cudaFuncAttributeMaxDynamicSharedMemorySize, SMEMSZ);
        cudaFuncSetAttribute(k_gemm<1,3>, cudaFuncAttributeMaxDynamicSharedMemorySize, SMEMSZ);
        cudaFuncSetAttribute(k_gemm<2,1>, cudaFuncAttributeMaxDynamicSharedMemorySize, SMEMSZ2);
        cudaFuncSetAttribute(k_gemm<3,1>, cudaFuncAttributeMaxDynamicSharedMemorySize, SMEMSZ);
        cudaStreamCreateWithFlags(&s1, cudaStreamNonBlocking);
        cudaEventCreateWithFlags(&e_fork, cudaEventDisableTiming);
        cudaEventCreateWithFlags(&e_sin,  cudaEventDisableTiming);
        cudaEventCreateWithFlags(&e_aux,  cudaEventDisableTiming);
        cudaEventCreateWithFlags(&e_base, cudaEventDisableTiming);
        cudaEventCreateWithFlags(&e_qk,   cudaEventDisableTiming);
        init_done = true;
    }

    fp16 *wh, *wl, *owh;
    cudaGetSymbolAddress((void**)&wh,  g_wh);
    cudaGetSymbolAddress((void**)&wl,  g_wl);
    cudaGetSymbolAddress((void**)&owh, g_owh);

    // ---- fork side stream from the (captured) legacy stream ----
    cudaEventRecord(e_fork, 0);
    cudaStreamWaitEvent(s1, e_fork, 0);

    // side stream: sincos + o_w split (independent prologue work)
    k_sincos<<<S_, 64, 0, s1>>>();
    cudaEventRecord(e_sin, s1);
    k_split <<<(H_*E_/4 + 255)/256, 256, 0, s1>>>(o_w, owh, nullptr, H_*E_/4);
    cudaEventRecord(e_aux, s1);

    // main stream: norm + uv_w split + uv base tile (3-pass, cols 2048..2175)
    k_norm  <<<M_, 128>>>(x, ln_g);
    k_split <<<(UV_*H_/4 + 255)/256, 256>>>(uv_w, wh, wl, UV_*H_/4);
    k_gemm<0,3><<<dim3(1, M_/128), 256, SMEMSZ>>>(uv_b, nullptr, nullptr, 2048);
    cudaEventRecord(e_base, 0);

    // side stream: rope (needs base + sincos) then qk — overlapped with uv main
    cudaStreamWaitEvent(s1, e_base, 0);
    k_rope  <<<M_, 64, 0, s1>>>(gam, bet);
    k_gemm<1,3><<<dim3(S_/128, S_/128, B_), 256, SMEMSZ, s1>>>(wb, nullptr, nullptr, 0);
    cudaEventRecord(e_qk, s1);

    // main stream: uv u/v tiles (1-pass) — runs concurrently with rope+qk
    k_gemm<0,1><<<dim3(16, M_/128), 256, SMEMSZ>>>(uv_b, nullptr, nullptr, 0);

    // join: pv needs qk (P) + uv main (u, v)
    cudaStreamWaitEvent(0, e_qk, 0);
    k_gemm<2,1><<<dim3(E_/128, S_/128, B_), 256, SMEMSZ2>>>(nullptr, nullptr, nullptr, 0);

    // join: out needs o_w split
    cudaStreamWaitEvent(0, e_aux, 0);
    k_gemm<3,1><<<dim3(H_/128, M_/128), 256, SMEMSZ>>>(o_b, x, out, 0);
}